// round 1
// baseline (speedup 1.0000x reference)
#include <cuda_runtime.h>
#include <math.h>

#define N_NODES 50000
#define N_EDGES 400000

// Scale constants
#define INV_S64  0.125f                  // 1/sqrt(64)
#define INV_S32  0.17677669529663687f    // 1/sqrt(32)
#define INV_S10  0.31622776601683794f    // 1/sqrt(10)
#define INV_S96  0.10206207261596575f    // 1/sqrt(96)
#define INV_S3   0.57735026918962576f    // 1/sqrt(3)

// ---------------- scratch (device globals; no allocation allowed) ----------
__device__ float d_hs [N_NODES * 64];   // lin1 scalar features
__device__ float d_hv [N_NODES * 96];   // lin1 vector features (32 x 3)
__device__ float d_scs[N_NODES * 96];   // skip-connection scalars (stride = OS)
__device__ float d_scv[N_NODES * 96];   // skip-connection vectors
__device__ float d_Ms [N_NODES * 96];   // aggregated scalar messages
__device__ float d_Mv [N_NODES * 288];  // aggregated vector messages (96 x 3)
__device__ float d_deg[N_NODES];
__device__ float d_gs [N_NODES * 64];   // layer-1 -> layer-2 scalar input
__device__ float d_v1 [N_NODES * 96];   // layer-1 -> layer-2 vector input

__device__ __forceinline__ float sigmoidf_(float x) { return 1.0f / (1.0f + __expf(-x)); }
__device__ __forceinline__ float siluf_(float x)    { return x / (1.0f + __expf(-x)); }

__device__ __forceinline__ void red4(float* p, float4 v) {
    // vectorized global reduction (sm_90+): one 16B red instead of 4 scalar atomics
    atomicAdd(reinterpret_cast<float4*>(p), v);
}

// ---------------- degree ---------------------------------------------------
__global__ void k_deg_zero() {
    int i = blockIdx.x * blockDim.x + threadIdx.x;
    if (i < N_NODES) d_deg[i] = 0.0f;
}
__global__ void k_deg(const int* __restrict__ dst) {
    int i = blockIdx.x * blockDim.x + threadIdx.x;
    if (i < N_EDGES) atomicAdd(&d_deg[dst[i]], 1.0f);
}

// ---------------- kernel A: node pre-linears (warp per node) ---------------
// hs = ns@W1s * attr/8 ; hv = einsum(nv,W1v)*attr/sqrt32 ; sc_s/sc_v likewise.
// Also zeroes Ms/Mv rows for this node.
template <int OS, bool SCR>
__global__ void __launch_bounds__(256) k_node_pre(
    const float* __restrict__ ns_in, const float* __restrict__ nv_in,
    const float* __restrict__ attr,
    const float* __restrict__ Wscs, const float* __restrict__ Wscv,
    const float* __restrict__ W1s,  const float* __restrict__ W1v)
{
    int n = blockIdx.x * 8 + (threadIdx.x >> 5);
    if (n >= N_NODES) return;
    int l = threadIdx.x & 31;

    const float* ns = SCR ? d_gs : ns_in;
    const float* nv = SCR ? d_v1 : nv_in;

    float a = attr[n];
    float ns0 = ns[n * 64 + l], ns1 = ns[n * 64 + 32 + l];
    float nv0 = nv[n * 96 + l * 3 + 0];
    float nv1 = nv[n * 96 + l * 3 + 1];
    float nv2 = nv[n * 96 + l * 3 + 2];

    float hs0 = 0.f, hs1 = 0.f;
    float sc0 = 0.f, sc1 = 0.f, sc2 = 0.f;
#pragma unroll
    for (int u = 0; u < 64; ++u) {
        float nsu = __shfl_sync(0xffffffffu, (u < 32) ? ns0 : ns1, u & 31);
        hs0 += nsu * W1s[u * 64 + l];
        hs1 += nsu * W1s[u * 64 + 32 + l];
        sc0 += nsu * Wscs[u * OS + l];
        sc1 += nsu * Wscs[u * OS + 32 + l];
        if (OS == 96) sc2 += nsu * Wscs[u * OS + 64 + l];
    }

    float hv0 = 0.f, hv1 = 0.f, hv2 = 0.f;
    float sv0 = 0.f, sv1 = 0.f, sv2 = 0.f;
#pragma unroll
    for (int u = 0; u < 32; ++u) {
        float b0 = __shfl_sync(0xffffffffu, nv0, u);
        float b1 = __shfl_sync(0xffffffffu, nv1, u);
        float b2 = __shfl_sync(0xffffffffu, nv2, u);
        float wl = W1v [u * 32 + l];
        float ws = Wscv[u * 32 + l];
        hv0 += b0 * wl; hv1 += b1 * wl; hv2 += b2 * wl;
        sv0 += b0 * ws; sv1 += b1 * ws; sv2 += b2 * ws;
    }

    float fs = a * INV_S64, fv = a * INV_S32;
    d_hs[n * 64 + l]       = hs0 * fs;
    d_hs[n * 64 + 32 + l]  = hs1 * fs;
    d_scs[n * OS + l]      = sc0 * fs;
    d_scs[n * OS + 32 + l] = sc1 * fs;
    if (OS == 96) d_scs[n * OS + 64 + l] = sc2 * fs;
    d_hv [n * 96 + l * 3 + 0] = hv0 * fv;
    d_hv [n * 96 + l * 3 + 1] = hv1 * fv;
    d_hv [n * 96 + l * 3 + 2] = hv2 * fv;
    d_scv[n * 96 + l * 3 + 0] = sv0 * fv;
    d_scv[n * 96 + l * 3 + 1] = sv1 * fv;
    d_scv[n * 96 + l * 3 + 2] = sv2 * fv;

    // zero accumulators for the edge pass
    d_Ms[n * 96 + l] = 0.f;
    d_Ms[n * 96 + 32 + l] = 0.f;
    d_Ms[n * 96 + 64 + l] = 0.f;
#pragma unroll
    for (int r = 0; r < 9; ++r) d_Mv[n * 288 + r * 32 + l] = 0.f;
}

// ---------------- kernel B: fused edge MLP + messages + scatter ------------
// 32 edges / block, 128 threads.
// smem: Wfc1(640) | Wfc2(12288) | esc(320) | h(2048) | w(6144) = 21440 floats
#define B_SMEM_FLOATS 21440
#define B_SMEM_BYTES  (B_SMEM_FLOATS * 4)

__global__ void __launch_bounds__(128) k_edge(
    const float* __restrict__ esc, const float* __restrict__ sh,
    const int* __restrict__ src,   const int* __restrict__ dst,
    const float* __restrict__ Wfc1, const float* __restrict__ Wfc2)
{
    extern __shared__ float sm[];
    float* s_w1  = sm;              // 640   : Wfc1 (10 x 64)
    float* s_w2  = sm + 640;        // 12288 : Wfc2 (64 x 192)
    float* s_esc = sm + 12928;      // 320   : edge scalars (32 x 10)
    float* s_h   = sm + 13248;      // 2048  : hidden (32 x 64)
    float* s_w   = sm + 15296;      // 6144  : weights w (32 x 192)

    int t  = threadIdx.x;
    int e0 = blockIdx.x * 32;

    for (int i = t; i < 640; i += 128) s_w1[i] = Wfc1[i];
    {
        const float4* g = (const float4*)Wfc2;
        float4* s = (float4*)s_w2;
        for (int i = t; i < 3072; i += 128) s[i] = g[i];
    }
    for (int i = t; i < 320; i += 128) s_esc[i] = esc[e0 * 10 + i];
    __syncthreads();

    // ---- phase 1: h = silu(esc @ Wfc1 / sqrt(10)) ----
    {
        int e = t & 31, q = t >> 5;     // warp-uniform q
        float es[10];
#pragma unroll
        for (int u = 0; u < 10; ++u) es[u] = s_esc[e * 10 + u];
#pragma unroll
        for (int c = 0; c < 16; ++c) {
            int col = q * 16 + c;
            float acc = 0.f;
#pragma unroll
            for (int u = 0; u < 10; ++u) acc += es[u] * s_w1[u * 64 + col];
            acc *= INV_S10;
            s_h[e * 64 + col] = siluf_(acc);
        }
    }
    __syncthreads();

    // ---- phase 2: w = h @ Wfc2 / 8  (4-edge x 12-col register tile) ----
    {
        int te = t >> 4, tc = t & 15;
        int eb = te * 4, c0 = tc * 12;
        float acc[48];
#pragma unroll
        for (int i = 0; i < 48; ++i) acc[i] = 0.f;
#pragma unroll 8
        for (int k = 0; k < 64; ++k) {
            float4 b0 = *(const float4*)(s_w2 + k * 192 + c0);
            float4 b1 = *(const float4*)(s_w2 + k * 192 + c0 + 4);
            float4 b2 = *(const float4*)(s_w2 + k * 192 + c0 + 8);
            float bb[12] = {b0.x, b0.y, b0.z, b0.w, b1.x, b1.y, b1.z, b1.w,
                            b2.x, b2.y, b2.z, b2.w};
#pragma unroll
            for (int r = 0; r < 4; ++r) {
                float av = s_h[(eb + r) * 64 + k];
#pragma unroll
                for (int c = 0; c < 12; ++c) acc[r * 12 + c] += av * bb[c];
            }
        }
#pragma unroll
        for (int r = 0; r < 4; ++r)
#pragma unroll
            for (int c = 0; c < 12; ++c)
                s_w[(eb + r) * 192 + c0 + c] = acc[r * 12 + c] * INV_S64;
    }
    __syncthreads();

    // ---- phase 3: messages + vector-atomic scatter ----
    {
        int e = t & 31, p = t >> 5;   // warp p handles channel block p (no divergence)
        int ge = e0 + e;
        int sn = src[ge], dn = dst[ge];
        float s0 = sh[ge * 4 + 0];
        float vx = sh[ge * 4 + 1], vy = sh[ge * 4 + 2], vz = sh[ge * 4 + 3];
        const float* hsp = d_hs + sn * 64;
        const float* hvp = d_hv + sn * 96;
        float* msd = d_Ms + dn * 96;
        float* mvd = d_Mv + dn * 288;
        const float* we = s_w + e * 192;

#pragma unroll
        for (int g = 0; g < 6; ++g) {
            int j0 = p * 24 + g * 4;
            if (j0 < 64) {
                float4 gs4 = *(const float4*)(hsp + j0);
                float4 w1  = *(const float4*)(we + j0);
                float4 w2  = *(const float4*)(we + 64 + j0);
                red4(msd + j0, make_float4(gs4.x * s0 * w1.x, gs4.y * s0 * w1.y,
                                           gs4.z * s0 * w1.z, gs4.w * s0 * w1.w));
                float gw0 = gs4.x * w2.x, gw1 = gs4.y * w2.y;
                float gw2 = gs4.z * w2.z, gw3 = gs4.w * w2.w;
                red4(mvd + j0 * 3 + 0, make_float4(gw0 * vx, gw0 * vy, gw0 * vz, gw1 * vx));
                red4(mvd + j0 * 3 + 4, make_float4(gw1 * vy, gw1 * vz, gw2 * vx, gw2 * vy));
                red4(mvd + j0 * 3 + 8, make_float4(gw2 * vz, gw3 * vx, gw3 * vy, gw3 * vz));
            } else {
                int jp = j0 - 64;
                const float* gp = hvp + jp * 3;
                float4 ga = *(const float4*)(gp);
                float4 gb = *(const float4*)(gp + 4);
                float4 gc = *(const float4*)(gp + 8);
                float gv[12] = {ga.x, ga.y, ga.z, ga.w, gb.x, gb.y, gb.z, gb.w,
                                gc.x, gc.y, gc.z, gc.w};
                float4 w4 = *(const float4*)(we + 160 + jp);
                float4 w3 = *(const float4*)(we + 128 + jp);
                float w4a[4] = {w4.x, w4.y, w4.z, w4.w};
                float w3a[4] = {w3.x, w3.y, w3.z, w3.w};
                float mso[4];
#pragma unroll
                for (int r = 0; r < 4; ++r)
                    mso[r] = (gv[r*3] * vx + gv[r*3+1] * vy + gv[r*3+2] * vz) * INV_S3 * w4a[r];
                red4(msd + 64 + jp, make_float4(mso[0], mso[1], mso[2], mso[3]));
                float mv[12];
#pragma unroll
                for (int r = 0; r < 4; ++r) {
                    float c = s0 * w3a[r];
                    mv[r*3] = gv[r*3] * c; mv[r*3+1] = gv[r*3+1] * c; mv[r*3+2] = gv[r*3+2] * c;
                }
                red4(mvd + 192 + jp * 3 + 0, make_float4(mv[0], mv[1], mv[2],  mv[3]));
                red4(mvd + 192 + jp * 3 + 4, make_float4(mv[4], mv[5], mv[6],  mv[7]));
                red4(mvd + 192 + jp * 3 + 8, make_float4(mv[8], mv[9], mv[10], mv[11]));
            }
        }
    }
}

// ---------------- kernel C: node finalize (warp per node) ------------------
template <int OS, bool L1>
__global__ void __launch_bounds__(256) k_node_post(
    const float* __restrict__ attr,
    const float* __restrict__ W2s, const float* __restrict__ W2v,
    const float* __restrict__ Wa,  float* __restrict__ out)
{
    int n = blockIdx.x * 8 + (threadIdx.x >> 5);
    if (n >= N_NODES) return;
    int l = threadIdx.x & 31;

    float a = attr[n];
    float invd = 1.0f / fmaxf(d_deg[n], 1.0f);

    float ms[3], mv[3][3];
#pragma unroll
    for (int r = 0; r < 3; ++r) {
        ms[r] = d_Ms[n * 96 + r * 32 + l] * invd;
#pragma unroll
        for (int i = 0; i < 3; ++i)
            mv[r][i] = d_Mv[n * 288 + (r * 32 + l) * 3 + i] * invd;
    }

    // alpha = (Ms . Wa) / sqrt(96) * attr
    float ap = ms[0] * Wa[l] + ms[1] * Wa[32 + l] + ms[2] * Wa[64 + l];
#pragma unroll
    for (int o = 16; o > 0; o >>= 1) ap += __shfl_xor_sync(0xffffffffu, ap, o);
    float alpha = ap * INV_S96 * a;

    float os0 = 0.f, os1 = 0.f, os2 = 0.f;
    float ov0 = 0.f, ov1 = 0.f, ov2 = 0.f;
#pragma unroll
    for (int u = 0; u < 96; ++u) {
        int r = u >> 5, lu = u & 31;
        float msu = __shfl_sync(0xffffffffu, ms[r], lu);
        float m0  = __shfl_sync(0xffffffffu, mv[r][0], lu);
        float m1  = __shfl_sync(0xffffffffu, mv[r][1], lu);
        float m2  = __shfl_sync(0xffffffffu, mv[r][2], lu);
        os0 += msu * W2s[u * OS + l];
        os1 += msu * W2s[u * OS + 32 + l];
        if (OS == 96) os2 += msu * W2s[u * OS + 64 + l];
        float wv = W2v[u * 32 + l];
        ov0 += m0 * wv; ov1 += m1 * wv; ov2 += m2 * wv;
    }

    float f = a * INV_S96;
    float sA = d_scs[n * OS + l]       + alpha * (os0 * f);
    float sB = d_scs[n * OS + 32 + l]  + alpha * (os1 * f);
    float sC = (OS == 96) ? (d_scs[n * OS + 64 + l] + alpha * (os2 * f)) : 0.f;
    float vv0 = d_scv[n * 96 + l * 3 + 0] + alpha * (ov0 * f);
    float vv1 = d_scv[n * 96 + l * 3 + 1] + alpha * (ov1 * f);
    float vv2 = d_scv[n * 96 + l * 3 + 2] + alpha * (ov2 * f);

    if (L1) {
        d_gs[n * 64 + l]      = siluf_(sA);
        d_gs[n * 64 + 32 + l] = siluf_(sB);
        float sg = sigmoidf_(sC);            // gate channels 64..95
        d_v1[n * 96 + l * 3 + 0] = vv0 * sg;
        d_v1[n * 96 + l * 3 + 1] = vv1 * sg;
        d_v1[n * 96 + l * 3 + 2] = vv2 * sg;
    } else {
        out[n * 160 + l]      = sA;
        out[n * 160 + 32 + l] = sB;
        out[n * 160 + 64 + l * 3 + 0] = vv0;
        out[n * 160 + 64 + l * 3 + 1] = vv1;
        out[n * 160 + 64 + l * 3 + 2] = vv2;
    }
}

// ---------------- launch ----------------------------------------------------
extern "C" void kernel_launch(void* const* d_in, const int* in_sizes, int n_in,
                              void* d_out, int out_size)
{
    const float* node_s = (const float*)d_in[0];
    const float* node_v = (const float*)d_in[1];
    const float* attr   = (const float*)d_in[2];
    const int*   src    = (const int*)d_in[3];
    const int*   dst    = (const int*)d_in[4];
    const float* sh     = (const float*)d_in[5];
    const float* esc    = (const float*)d_in[6];
    const float* w1[9];
    const float* w2[9];
    for (int i = 0; i < 9; ++i) { w1[i] = (const float*)d_in[7 + i]; w2[i] = (const float*)d_in[16 + i]; }
    float* out = (float*)d_out;

    cudaFuncSetAttribute(k_edge, cudaFuncAttributeMaxDynamicSharedMemorySize, B_SMEM_BYTES);

    k_deg_zero<<<(N_NODES + 255) / 256, 256>>>();
    k_deg<<<(N_EDGES + 255) / 256, 256>>>(dst);

    // ---- layer 1 (o_s = 96) ----
    k_node_pre<96, false><<<(N_NODES + 7) / 8, 256>>>(node_s, node_v, attr,
                                                      w1[0], w1[1], w1[2], w1[3]);
    k_edge<<<N_EDGES / 32, 128, B_SMEM_BYTES>>>(esc, sh, src, dst, w1[4], w1[5]);
    k_node_post<96, true><<<(N_NODES + 7) / 8, 256>>>(attr, w1[6], w1[7], w1[8], out);

    // ---- layer 2 (o_s = 64) ----
    k_node_pre<64, true><<<(N_NODES + 7) / 8, 256>>>(nullptr, nullptr, attr,
                                                     w2[0], w2[1], w2[2], w2[3]);
    k_edge<<<N_EDGES / 32, 128, B_SMEM_BYTES>>>(esc, sh, src, dst, w2[4], w2[5]);
    k_node_post<64, false><<<(N_NODES + 7) / 8, 256>>>(attr, w2[6], w2[7], w2[8], out);

    (void)in_sizes; (void)n_in; (void)out_size;
}

// round 2
// speedup vs baseline: 1.1524x; 1.1524x over previous
#include <cuda_runtime.h>
#include <math.h>

#define N_NODES 50000
#define N_EDGES 400000
#define EPB 64   // edges per block in k_edge

// Scale constants
#define INV_S64  0.125f                  // 1/sqrt(64)
#define INV_S32  0.17677669529663687f    // 1/sqrt(32)
#define INV_S10  0.31622776601683794f    // 1/sqrt(10)
#define INV_S96  0.10206207261596575f    // 1/sqrt(96)
#define INV_S3   0.57735026918962576f    // 1/sqrt(3)

// ---------------- scratch (device globals; no allocation allowed) ----------
__device__ float d_hs [N_NODES * 64];   // lin1 scalar features
__device__ float d_hv [N_NODES * 96];   // lin1 vector features (32 x 3)
__device__ float d_scs[N_NODES * 96];   // skip-connection scalars (stride = OS)
__device__ float d_scv[N_NODES * 96];   // skip-connection vectors
__device__ float d_Ms [N_NODES * 96];   // aggregated scalar messages
__device__ float d_Mv [N_NODES * 288];  // aggregated vector messages (96 x 3)
__device__ float d_deg[N_NODES];
__device__ float d_gs [N_NODES * 64];   // layer-1 -> layer-2 scalar input
__device__ float d_v1 [N_NODES * 96];   // layer-1 -> layer-2 vector input

__device__ __forceinline__ float sigmoidf_(float x) { return 1.0f / (1.0f + __expf(-x)); }
__device__ __forceinline__ float siluf_(float x)    { return x / (1.0f + __expf(-x)); }

// ---------------- degree ---------------------------------------------------
__global__ void k_deg_zero() {
    int i = blockIdx.x * blockDim.x + threadIdx.x;
    if (i < N_NODES) d_deg[i] = 0.0f;
}
__global__ void k_deg(const int* __restrict__ dst) {
    int i = blockIdx.x * blockDim.x + threadIdx.x;
    if (i < N_EDGES) atomicAdd(&d_deg[dst[i]], 1.0f);
}

// ---------------- kernel A: node pre-linears (warp per node) ---------------
template <int OS, bool SCR>
__global__ void __launch_bounds__(256) k_node_pre(
    const float* __restrict__ ns_in, const float* __restrict__ nv_in,
    const float* __restrict__ attr,
    const float* __restrict__ Wscs, const float* __restrict__ Wscv,
    const float* __restrict__ W1s,  const float* __restrict__ W1v)
{
    int n = blockIdx.x * 8 + (threadIdx.x >> 5);
    if (n >= N_NODES) return;
    int l = threadIdx.x & 31;

    const float* ns = SCR ? d_gs : ns_in;
    const float* nv = SCR ? d_v1 : nv_in;

    float a = attr[n];
    float ns0 = ns[n * 64 + l], ns1 = ns[n * 64 + 32 + l];
    float nv0 = nv[n * 96 + l * 3 + 0];
    float nv1 = nv[n * 96 + l * 3 + 1];
    float nv2 = nv[n * 96 + l * 3 + 2];

    float hs0 = 0.f, hs1 = 0.f;
    float sc0 = 0.f, sc1 = 0.f, sc2 = 0.f;
#pragma unroll
    for (int u = 0; u < 64; ++u) {
        float nsu = __shfl_sync(0xffffffffu, (u < 32) ? ns0 : ns1, u & 31);
        hs0 += nsu * W1s[u * 64 + l];
        hs1 += nsu * W1s[u * 64 + 32 + l];
        sc0 += nsu * Wscs[u * OS + l];
        sc1 += nsu * Wscs[u * OS + 32 + l];
        if (OS == 96) sc2 += nsu * Wscs[u * OS + 64 + l];
    }

    float hv0 = 0.f, hv1 = 0.f, hv2 = 0.f;
    float sv0 = 0.f, sv1 = 0.f, sv2 = 0.f;
#pragma unroll
    for (int u = 0; u < 32; ++u) {
        float b0 = __shfl_sync(0xffffffffu, nv0, u);
        float b1 = __shfl_sync(0xffffffffu, nv1, u);
        float b2 = __shfl_sync(0xffffffffu, nv2, u);
        float wl = W1v [u * 32 + l];
        float ws = Wscv[u * 32 + l];
        hv0 += b0 * wl; hv1 += b1 * wl; hv2 += b2 * wl;
        sv0 += b0 * ws; sv1 += b1 * ws; sv2 += b2 * ws;
    }

    float fs = a * INV_S64, fv = a * INV_S32;
    d_hs[n * 64 + l]       = hs0 * fs;
    d_hs[n * 64 + 32 + l]  = hs1 * fs;
    d_scs[n * OS + l]      = sc0 * fs;
    d_scs[n * OS + 32 + l] = sc1 * fs;
    if (OS == 96) d_scs[n * OS + 64 + l] = sc2 * fs;
    d_hv [n * 96 + l * 3 + 0] = hv0 * fv;
    d_hv [n * 96 + l * 3 + 1] = hv1 * fv;
    d_hv [n * 96 + l * 3 + 2] = hv2 * fv;
    d_scv[n * 96 + l * 3 + 0] = sv0 * fv;
    d_scv[n * 96 + l * 3 + 1] = sv1 * fv;
    d_scv[n * 96 + l * 3 + 2] = sv2 * fv;

    // zero accumulators for the edge pass
    d_Ms[n * 96 + l] = 0.f;
    d_Ms[n * 96 + 32 + l] = 0.f;
    d_Ms[n * 96 + 64 + l] = 0.f;
#pragma unroll
    for (int r = 0; r < 9; ++r) d_Mv[n * 288 + r * 32 + l] = 0.f;
}

// ---------------- kernel B: fused edge MLP + messages + scatter ------------
// 64 edges / block, 256 threads.
// smem floats: Wfc1 640 | esc 640 | h 64*65=4160 | w 64*193=12352 | chunk 16*192=3072
#define B_SMEM_FLOATS (640 + 640 + 64*65 + 64*193 + 16*192)   // 20864
#define B_SMEM_BYTES  (B_SMEM_FLOATS * 4)                     // 83456

__global__ void __launch_bounds__(256, 2) k_edge(
    const float* __restrict__ esc, const float* __restrict__ sh,
    const int* __restrict__ src,   const int* __restrict__ dst,
    const float* __restrict__ Wfc1, const float* __restrict__ Wfc2)
{
    extern __shared__ float sm[];
    float* s_w1    = sm;                 // 640   : Wfc1 (10 x 64)
    float* s_esc   = sm + 640;           // 640   : edge scalars (64 x 10)
    float* s_h     = sm + 1280;          // 4160  : hidden (64 rows, stride 65)
    float* s_w     = sm + 5440;          // 12352 : weights w (64 rows, stride 193)
    float* s_chunk = sm + 17792;         // 3072  : Wfc2 k-chunk (16 x 192)

    const int t  = threadIdx.x;
    const int e0 = blockIdx.x * EPB;

    for (int i = t; i < 640; i += 256) s_w1[i]  = Wfc1[i];
    for (int i = t; i < 640; i += 256) s_esc[i] = esc[e0 * 10 + i];
    __syncthreads();

    // ---- phase 1: h = silu(esc @ Wfc1 / sqrt(10)) ----
    {
        int e = t & 63, q = t >> 6;     // 4 col-groups of 16
        float es[10];
#pragma unroll
        for (int u = 0; u < 10; ++u) es[u] = s_esc[e * 10 + u];
#pragma unroll
        for (int c = 0; c < 16; ++c) {
            int col = q * 16 + c;
            float acc = 0.f;
#pragma unroll
            for (int u = 0; u < 10; ++u) acc += es[u] * s_w1[u * 64 + col];
            s_h[e * 65 + col] = siluf_(acc * INV_S10);
        }
    }
    // (ordering: first chunk-loop __syncthreads covers the s_h writes)

    // ---- phase 2: w = h @ Wfc2 / 8 ----
    // warp owns 24 columns (uniform chunk reads), lane owns edges {lane, lane+32}
    {
        const int lane = t & 31, wp = t >> 5;
        const int c0 = wp * 24;
        float acc0[24], acc1[24];
#pragma unroll
        for (int i = 0; i < 24; ++i) { acc0[i] = 0.f; acc1[i] = 0.f; }

        for (int ch = 0; ch < 4; ++ch) {
            __syncthreads();
            {   // load 16 k-rows of Wfc2 into s_chunk
                const float4* g4 = (const float4*)(Wfc2 + ch * 16 * 192);
                float4* c4 = (float4*)s_chunk;
                for (int i = t; i < 768; i += 256) c4[i] = g4[i];
            }
            __syncthreads();
#pragma unroll
            for (int kk = 0; kk < 16; ++kk) {
                float a0 = s_h[lane * 65        + ch * 16 + kk];
                float a1 = s_h[(lane + 32) * 65 + ch * 16 + kk];
                const float4* bp = (const float4*)(s_chunk + kk * 192 + c0);
#pragma unroll
                for (int q4 = 0; q4 < 6; ++q4) {
                    float4 b = bp[q4];
                    acc0[q4 * 4 + 0] += a0 * b.x; acc1[q4 * 4 + 0] += a1 * b.x;
                    acc0[q4 * 4 + 1] += a0 * b.y; acc1[q4 * 4 + 1] += a1 * b.y;
                    acc0[q4 * 4 + 2] += a0 * b.z; acc1[q4 * 4 + 2] += a1 * b.z;
                    acc0[q4 * 4 + 3] += a0 * b.w; acc1[q4 * 4 + 3] += a1 * b.w;
                }
            }
        }
#pragma unroll
        for (int j = 0; j < 24; ++j) {
            s_w[lane * 193        + c0 + j] = acc0[j] * INV_S64;
            s_w[(lane + 32) * 193 + c0 + j] = acc1[j] * INV_S64;
        }
    }
    __syncthreads();

    // ---- phase 3: warp-per-edge messages + coalesced scalar scatter ----
    {
        const int lane = t & 31, wp = t >> 5;
#pragma unroll
        for (int ei = 0; ei < 8; ++ei) {
            int e  = wp * 8 + ei;
            int ge = e0 + e;
            int sn = __ldg(src + ge), dn = __ldg(dst + ge);
            float4 sh4 = __ldg((const float4*)(sh + ge * 4));
            float s0 = sh4.x, vx = sh4.y, vy = sh4.z, vz = sh4.w;
            const float* we  = s_w + e * 193;
            const float* hsp = d_hs + sn * 64;
            const float* hvp = d_hv + sn * 96;
            float* msd = d_Ms + dn * 96;
            float* mvd = d_Mv + dn * 288;

            // Ms channels 0..63 : gs * sh0 * w1
            atomicAdd(msd + lane,      hsp[lane]      * s0 * we[lane]);
            atomicAdd(msd + 32 + lane, hsp[lane + 32] * s0 * we[lane + 32]);
            // Ms channels 64..95 : (gv . shv)/sqrt3 * w4
            {
                float h0 = hvp[lane * 3], h1 = hvp[lane * 3 + 1], h2 = hvp[lane * 3 + 2];
                atomicAdd(msd + 64 + lane,
                          (h0 * vx + h1 * vy + h2 * vz) * INV_S3 * we[160 + lane]);
            }
            // Mv flat 0..191 : gs[j] * shv[i] * w2[j]   (j = f/3, i = f%3)
#pragma unroll
            for (int r = 0; r < 6; ++r) {
                int f = r * 32 + lane;
                int j = f / 3, i = f - 3 * j;
                float shvi = (i == 0) ? vx : ((i == 1) ? vy : vz);
                atomicAdd(mvd + f, hsp[j] * shvi * we[64 + j]);
            }
            // Mv flat 192..287 : gv[jp][i] * sh0 * w3[jp]  (idx = f-192 = jp*3+i)
#pragma unroll
            for (int r = 0; r < 3; ++r) {
                int idx = r * 32 + lane;
                atomicAdd(mvd + 192 + idx, hvp[idx] * s0 * we[128 + idx / 3]);
            }
        }
    }
}

// ---------------- kernel C: node finalize (warp per node) ------------------
template <int OS, bool L1>
__global__ void __launch_bounds__(256) k_node_post(
    const float* __restrict__ attr,
    const float* __restrict__ W2s, const float* __restrict__ W2v,
    const float* __restrict__ Wa,  float* __restrict__ out)
{
    int n = blockIdx.x * 8 + (threadIdx.x >> 5);
    if (n >= N_NODES) return;
    int l = threadIdx.x & 31;

    float a = attr[n];
    float invd = 1.0f / fmaxf(d_deg[n], 1.0f);

    float ms[3], mv[3][3];
#pragma unroll
    for (int r = 0; r < 3; ++r) {
        ms[r] = d_Ms[n * 96 + r * 32 + l] * invd;
#pragma unroll
        for (int i = 0; i < 3; ++i)
            mv[r][i] = d_Mv[n * 288 + (r * 32 + l) * 3 + i] * invd;
    }

    // alpha = (Ms . Wa) / sqrt(96) * attr
    float ap = ms[0] * Wa[l] + ms[1] * Wa[32 + l] + ms[2] * Wa[64 + l];
#pragma unroll
    for (int o = 16; o > 0; o >>= 1) ap += __shfl_xor_sync(0xffffffffu, ap, o);
    float alpha = ap * INV_S96 * a;

    float os0 = 0.f, os1 = 0.f, os2 = 0.f;
    float ov0 = 0.f, ov1 = 0.f, ov2 = 0.f;
#pragma unroll
    for (int u = 0; u < 96; ++u) {
        int r = u >> 5, lu = u & 31;
        float msu = __shfl_sync(0xffffffffu, ms[r], lu);
        float m0  = __shfl_sync(0xffffffffu, mv[r][0], lu);
        float m1  = __shfl_sync(0xffffffffu, mv[r][1], lu);
        float m2  = __shfl_sync(0xffffffffu, mv[r][2], lu);
        os0 += msu * W2s[u * OS + l];
        os1 += msu * W2s[u * OS + 32 + l];
        if (OS == 96) os2 += msu * W2s[u * OS + 64 + l];
        float wv = W2v[u * 32 + l];
        ov0 += m0 * wv; ov1 += m1 * wv; ov2 += m2 * wv;
    }

    float f = a * INV_S96;
    float sA = d_scs[n * OS + l]       + alpha * (os0 * f);
    float sB = d_scs[n * OS + 32 + l]  + alpha * (os1 * f);
    float sC = (OS == 96) ? (d_scs[n * OS + 64 + l] + alpha * (os2 * f)) : 0.f;
    float vv0 = d_scv[n * 96 + l * 3 + 0] + alpha * (ov0 * f);
    float vv1 = d_scv[n * 96 + l * 3 + 1] + alpha * (ov1 * f);
    float vv2 = d_scv[n * 96 + l * 3 + 2] + alpha * (ov2 * f);

    if (L1) {
        d_gs[n * 64 + l]      = siluf_(sA);
        d_gs[n * 64 + 32 + l] = siluf_(sB);
        float sg = sigmoidf_(sC);            // gate channels 64..95
        d_v1[n * 96 + l * 3 + 0] = vv0 * sg;
        d_v1[n * 96 + l * 3 + 1] = vv1 * sg;
        d_v1[n * 96 + l * 3 + 2] = vv2 * sg;
    } else {
        out[n * 160 + l]      = sA;
        out[n * 160 + 32 + l] = sB;
        out[n * 160 + 64 + l * 3 + 0] = vv0;
        out[n * 160 + 64 + l * 3 + 1] = vv1;
        out[n * 160 + 64 + l * 3 + 2] = vv2;
    }
}

// ---------------- launch ----------------------------------------------------
extern "C" void kernel_launch(void* const* d_in, const int* in_sizes, int n_in,
                              void* d_out, int out_size)
{
    const float* node_s = (const float*)d_in[0];
    const float* node_v = (const float*)d_in[1];
    const float* attr   = (const float*)d_in[2];
    const int*   src    = (const int*)d_in[3];
    const int*   dst    = (const int*)d_in[4];
    const float* sh     = (const float*)d_in[5];
    const float* esc    = (const float*)d_in[6];
    const float* w1[9];
    const float* w2[9];
    for (int i = 0; i < 9; ++i) { w1[i] = (const float*)d_in[7 + i]; w2[i] = (const float*)d_in[16 + i]; }
    float* out = (float*)d_out;

    cudaFuncSetAttribute(k_edge, cudaFuncAttributeMaxDynamicSharedMemorySize, B_SMEM_BYTES);

    k_deg_zero<<<(N_NODES + 255) / 256, 256>>>();
    k_deg<<<(N_EDGES + 255) / 256, 256>>>(dst);

    // ---- layer 1 (o_s = 96) ----
    k_node_pre<96, false><<<(N_NODES + 7) / 8, 256>>>(node_s, node_v, attr,
                                                      w1[0], w1[1], w1[2], w1[3]);
    k_edge<<<N_EDGES / EPB, 256, B_SMEM_BYTES>>>(esc, sh, src, dst, w1[4], w1[5]);
    k_node_post<96, true><<<(N_NODES + 7) / 8, 256>>>(attr, w1[6], w1[7], w1[8], out);

    // ---- layer 2 (o_s = 64) ----
    k_node_pre<64, true><<<(N_NODES + 7) / 8, 256>>>(nullptr, nullptr, attr,
                                                     w2[0], w2[1], w2[2], w2[3]);
    k_edge<<<N_EDGES / EPB, 256, B_SMEM_BYTES>>>(esc, sh, src, dst, w2[4], w2[5]);
    k_node_post<64, false><<<(N_NODES + 7) / 8, 256>>>(attr, w2[6], w2[7], w2[8], out);

    (void)in_sizes; (void)n_in; (void)out_size;
}

// round 3
// speedup vs baseline: 1.3675x; 1.1867x over previous
#include <cuda_runtime.h>
#include <math.h>
#include <stdint.h>

#define N_NODES 50000
#define N_EDGES 400000
#define EPB 64   // edges per block in k_edge

// Scale constants
#define INV_S64  0.125f                  // 1/sqrt(64)
#define INV_S32  0.17677669529663687f    // 1/sqrt(32)
#define INV_S10  0.31622776601683794f    // 1/sqrt(10)
#define INV_S96  0.10206207261596575f    // 1/sqrt(96)
#define INV_S3   0.57735026918962576f    // 1/sqrt(3)

// ---------------- scratch (device globals; no allocation allowed) ----------
__device__ float d_hs [N_NODES * 64];   // lin1 scalar features
__device__ float d_hv [N_NODES * 96];   // lin1 vector features (32 x 3)
__device__ float d_scs[N_NODES * 96];   // skip-connection scalars (stride = OS)
__device__ float d_scv[N_NODES * 96];   // skip-connection vectors
__device__ float d_Ms [N_NODES * 96];   // aggregated scalar messages
__device__ float d_Mv [N_NODES * 288];  // aggregated vector messages (96 x 3)
__device__ float d_deg[N_NODES];
__device__ float d_gs [N_NODES * 64];   // layer-1 -> layer-2 scalar input
__device__ float d_v1 [N_NODES * 96];   // layer-1 -> layer-2 vector input

__device__ __forceinline__ float sigmoidf_(float x) { return 1.0f / (1.0f + __expf(-x)); }
__device__ __forceinline__ float siluf_(float x)    { return x / (1.0f + __expf(-x)); }

__device__ __forceinline__ float tf32r(float x) {
    uint32_t u;
    asm("cvt.rna.tf32.f32 %0, %1;" : "=r"(u) : "f"(x));
    return __uint_as_float(u);
}

__device__ __forceinline__ void mma_tf32(float c[4],
    uint32_t a0, uint32_t a1, uint32_t a2, uint32_t a3,
    uint32_t b0, uint32_t b1)
{
    asm volatile(
        "mma.sync.aligned.m16n8k8.row.col.f32.tf32.tf32.f32 "
        "{%0,%1,%2,%3},{%4,%5,%6,%7},{%8,%9},{%0,%1,%2,%3};"
        : "+f"(c[0]), "+f"(c[1]), "+f"(c[2]), "+f"(c[3])
        : "r"(a0), "r"(a1), "r"(a2), "r"(a3), "r"(b0), "r"(b1));
}

// ---------------- degree ---------------------------------------------------
__global__ void k_deg_zero() {
    int i = blockIdx.x * blockDim.x + threadIdx.x;
    if (i < N_NODES) d_deg[i] = 0.0f;
}
__global__ void k_deg(const int* __restrict__ dst) {
    int i = blockIdx.x * blockDim.x + threadIdx.x;
    if (i < N_EDGES) atomicAdd(&d_deg[dst[i]], 1.0f);
}

// ---------------- kernel A: node pre-linears (warp per node) ---------------
template <int OS, bool SCR>
__global__ void __launch_bounds__(256) k_node_pre(
    const float* __restrict__ ns_in, const float* __restrict__ nv_in,
    const float* __restrict__ attr,
    const float* __restrict__ Wscs, const float* __restrict__ Wscv,
    const float* __restrict__ W1s,  const float* __restrict__ W1v)
{
    int n = blockIdx.x * 8 + (threadIdx.x >> 5);
    if (n >= N_NODES) return;
    int l = threadIdx.x & 31;

    const float* ns = SCR ? d_gs : ns_in;
    const float* nv = SCR ? d_v1 : nv_in;

    float a = attr[n];
    float ns0 = ns[n * 64 + l], ns1 = ns[n * 64 + 32 + l];
    float nv0 = nv[n * 96 + l * 3 + 0];
    float nv1 = nv[n * 96 + l * 3 + 1];
    float nv2 = nv[n * 96 + l * 3 + 2];

    float hs0 = 0.f, hs1 = 0.f;
    float sc0 = 0.f, sc1 = 0.f, sc2 = 0.f;
#pragma unroll
    for (int u = 0; u < 64; ++u) {
        float nsu = __shfl_sync(0xffffffffu, (u < 32) ? ns0 : ns1, u & 31);
        hs0 += nsu * W1s[u * 64 + l];
        hs1 += nsu * W1s[u * 64 + 32 + l];
        sc0 += nsu * Wscs[u * OS + l];
        sc1 += nsu * Wscs[u * OS + 32 + l];
        if (OS == 96) sc2 += nsu * Wscs[u * OS + 64 + l];
    }

    float hv0 = 0.f, hv1 = 0.f, hv2 = 0.f;
    float sv0 = 0.f, sv1 = 0.f, sv2 = 0.f;
#pragma unroll
    for (int u = 0; u < 32; ++u) {
        float b0 = __shfl_sync(0xffffffffu, nv0, u);
        float b1 = __shfl_sync(0xffffffffu, nv1, u);
        float b2 = __shfl_sync(0xffffffffu, nv2, u);
        float wl = W1v [u * 32 + l];
        float ws = Wscv[u * 32 + l];
        hv0 += b0 * wl; hv1 += b1 * wl; hv2 += b2 * wl;
        sv0 += b0 * ws; sv1 += b1 * ws; sv2 += b2 * ws;
    }

    float fs = a * INV_S64, fv = a * INV_S32;
    d_hs[n * 64 + l]       = hs0 * fs;
    d_hs[n * 64 + 32 + l]  = hs1 * fs;
    d_scs[n * OS + l]      = sc0 * fs;
    d_scs[n * OS + 32 + l] = sc1 * fs;
    if (OS == 96) d_scs[n * OS + 64 + l] = sc2 * fs;
    d_hv [n * 96 + l * 3 + 0] = hv0 * fv;
    d_hv [n * 96 + l * 3 + 1] = hv1 * fv;
    d_hv [n * 96 + l * 3 + 2] = hv2 * fv;
    d_scv[n * 96 + l * 3 + 0] = sv0 * fv;
    d_scv[n * 96 + l * 3 + 1] = sv1 * fv;
    d_scv[n * 96 + l * 3 + 2] = sv2 * fv;

    // zero accumulators for the edge pass
    d_Ms[n * 96 + l] = 0.f;
    d_Ms[n * 96 + 32 + l] = 0.f;
    d_Ms[n * 96 + 64 + l] = 0.f;
#pragma unroll
    for (int r = 0; r < 9; ++r) d_Mv[n * 288 + r * 32 + l] = 0.f;
}

// ---------------- kernel B: fused edge MLP (tf32 MMA) + messages + scatter -
// 64 edges / block, 256 threads (8 warps).
// smem floats: Wfc1 640 | esc 640 | hT 64*72 (k-major, stride 72)
//              | w 64*193 | chunk 16*200
#define SH_STRIDE 72
#define CH_STRIDE 200
#define B_SMEM_FLOATS (640 + 640 + 64*SH_STRIDE + 64*193 + 16*CH_STRIDE) // 21440
#define B_SMEM_BYTES  (B_SMEM_FLOATS * 4)                                // 85760

__global__ void __launch_bounds__(256, 2) k_edge(
    const float* __restrict__ esc, const float* __restrict__ sh,
    const int* __restrict__ src,   const int* __restrict__ dst,
    const float* __restrict__ Wfc1, const float* __restrict__ Wfc2)
{
    extern __shared__ float sm[];
    float* s_w1    = sm;                        // 640  : Wfc1 (10 x 64)
    float* s_esc   = sm + 640;                  // 640  : edge scalars (64 x 10)
    float* s_hT    = sm + 1280;                 // 4608 : hidden, TRANSPOSED [64 k][72]
    float* s_w     = sm + 1280 + 64*SH_STRIDE;  // 12352: weights w (64 rows, stride 193)
    float* s_chunk = s_w + 64*193;              // 3200 : Wfc2 k-chunk (16 x 200)

    const int t  = threadIdx.x;
    const int e0 = blockIdx.x * EPB;
    const int lane = t & 31, wp = t >> 5;

    for (int i = t; i < 640; i += 256) s_w1[i]  = Wfc1[i];
    for (int i = t; i < 640; i += 256) s_esc[i] = esc[e0 * 10 + i];
    __syncthreads();

    // ---- phase 1: h = silu(esc @ Wfc1 / sqrt(10)), tf32-rounded, transposed ----
    {
        int e = t & 63, q = t >> 6;     // 4 col-groups of 16
        float es[10];
#pragma unroll
        for (int u = 0; u < 10; ++u) es[u] = s_esc[e * 10 + u];
#pragma unroll
        for (int c = 0; c < 16; ++c) {
            int col = q * 16 + c;
            float acc = 0.f;
#pragma unroll
            for (int u = 0; u < 10; ++u) acc += es[u] * s_w1[u * 64 + col];
            s_hT[col * SH_STRIDE + e] = tf32r(siluf_(acc * INV_S10));
        }
    }
    // (first chunk-loop __syncthreads covers the s_hT writes)

    // ---- phase 2: w = h @ Wfc2 / 8 via tf32 m16n8k8 MMA ----
    // warp wp: m-tile (wp&3)*16, n-half (wp>>2)*96 -> 12 n-tiles of 8, K=64
    {
        const int m0  = (wp & 3) * 16;
        const int nb  = (wp >> 2) * 96;
        const int row = lane >> 2, kc = lane & 3;

        float c[12][4];
#pragma unroll
        for (int i = 0; i < 12; ++i)
#pragma unroll
            for (int j = 0; j < 4; ++j) c[i][j] = 0.f;

        for (int ch = 0; ch < 4; ++ch) {
            __syncthreads();
            {   // load 16 k-rows of Wfc2, tf32-rounded, into s_chunk (stride 200)
                const float4* g4 = (const float4*)(Wfc2 + ch * 16 * 192);
                for (int i = t; i < 768; i += 256) {
                    float4 v = g4[i];
                    v.x = tf32r(v.x); v.y = tf32r(v.y);
                    v.z = tf32r(v.z); v.w = tf32r(v.w);
                    int r = i / 48, c4 = i % 48;
                    ((float4*)(s_chunk + r * CH_STRIDE))[c4] = v;
                }
            }
            __syncthreads();
#pragma unroll
            for (int ks = 0; ks < 2; ++ks) {
                int kk = ch * 16 + ks * 8;
                uint32_t a0 = __float_as_uint(s_hT[(kk + kc)     * SH_STRIDE + m0 + row]);
                uint32_t a1 = __float_as_uint(s_hT[(kk + kc)     * SH_STRIDE + m0 + row + 8]);
                uint32_t a2 = __float_as_uint(s_hT[(kk + kc + 4) * SH_STRIDE + m0 + row]);
                uint32_t a3 = __float_as_uint(s_hT[(kk + kc + 4) * SH_STRIDE + m0 + row + 8]);
#pragma unroll
                for (int tn = 0; tn < 12; ++tn) {
                    int n0 = nb + tn * 8;
                    uint32_t b0 = __float_as_uint(s_chunk[(ks * 8 + kc)     * CH_STRIDE + n0 + row]);
                    uint32_t b1 = __float_as_uint(s_chunk[(ks * 8 + kc + 4) * CH_STRIDE + n0 + row]);
                    mma_tf32(c[tn], a0, a1, a2, a3, b0, b1);
                }
            }
        }
        // writeback C -> s_w (row r: edge, col: weight channel), scaled by 1/8
#pragma unroll
        for (int tn = 0; tn < 12; ++tn) {
            int col = nb + tn * 8 + kc * 2;
            int r0 = m0 + row;
            s_w[r0 * 193 + col]           = c[tn][0] * INV_S64;
            s_w[r0 * 193 + col + 1]       = c[tn][1] * INV_S64;
            s_w[(r0 + 8) * 193 + col]     = c[tn][2] * INV_S64;
            s_w[(r0 + 8) * 193 + col + 1] = c[tn][3] * INV_S64;
        }
    }
    __syncthreads();

    // ---- phase 3: warp-per-edge messages + coalesced scalar scatter ----
    {
#pragma unroll
        for (int ei = 0; ei < 8; ++ei) {
            int e  = wp * 8 + ei;
            int ge = e0 + e;
            int sn = __ldg(src + ge), dn = __ldg(dst + ge);
            float4 sh4 = __ldg((const float4*)(sh + ge * 4));
            float s0 = sh4.x, vx = sh4.y, vy = sh4.z, vz = sh4.w;
            const float* we  = s_w + e * 193;
            const float* hsp = d_hs + sn * 64;
            const float* hvp = d_hv + sn * 96;
            float* msd = d_Ms + dn * 96;
            float* mvd = d_Mv + dn * 288;

            // Ms channels 0..63 : gs * sh0 * w1
            atomicAdd(msd + lane,      hsp[lane]      * s0 * we[lane]);
            atomicAdd(msd + 32 + lane, hsp[lane + 32] * s0 * we[lane + 32]);
            // Ms channels 64..95 : (gv . shv)/sqrt3 * w4
            {
                float h0 = hvp[lane * 3], h1 = hvp[lane * 3 + 1], h2 = hvp[lane * 3 + 2];
                atomicAdd(msd + 64 + lane,
                          (h0 * vx + h1 * vy + h2 * vz) * INV_S3 * we[160 + lane]);
            }
            // Mv flat 0..191 : gs[j] * shv[i] * w2[j]   (j = f/3, i = f%3)
#pragma unroll
            for (int r = 0; r < 6; ++r) {
                int f = r * 32 + lane;
                int j = f / 3, i = f - 3 * j;
                float shvi = (i == 0) ? vx : ((i == 1) ? vy : vz);
                atomicAdd(mvd + f, hsp[j] * shvi * we[64 + j]);
            }
            // Mv flat 192..287 : gv[jp][i] * sh0 * w3[jp]  (idx = jp*3+i)
#pragma unroll
            for (int r = 0; r < 3; ++r) {
                int idx = r * 32 + lane;
                atomicAdd(mvd + 192 + idx, hvp[idx] * s0 * we[128 + idx / 3]);
            }
        }
    }
}

// ---------------- kernel C: node finalize (warp per node) ------------------
template <int OS, bool L1>
__global__ void __launch_bounds__(256) k_node_post(
    const float* __restrict__ attr,
    const float* __restrict__ W2s, const float* __restrict__ W2v,
    const float* __restrict__ Wa,  float* __restrict__ out)
{
    int n = blockIdx.x * 8 + (threadIdx.x >> 5);
    if (n >= N_NODES) return;
    int l = threadIdx.x & 31;

    float a = attr[n];
    float invd = 1.0f / fmaxf(d_deg[n], 1.0f);

    float ms[3], mv[3][3];
#pragma unroll
    for (int r = 0; r < 3; ++r) {
        ms[r] = d_Ms[n * 96 + r * 32 + l] * invd;
#pragma unroll
        for (int i = 0; i < 3; ++i)
            mv[r][i] = d_Mv[n * 288 + (r * 32 + l) * 3 + i] * invd;
    }

    // alpha = (Ms . Wa) / sqrt(96) * attr
    float ap = ms[0] * Wa[l] + ms[1] * Wa[32 + l] + ms[2] * Wa[64 + l];
#pragma unroll
    for (int o = 16; o > 0; o >>= 1) ap += __shfl_xor_sync(0xffffffffu, ap, o);
    float alpha = ap * INV_S96 * a;

    float os0 = 0.f, os1 = 0.f, os2 = 0.f;
    float ov0 = 0.f, ov1 = 0.f, ov2 = 0.f;
#pragma unroll
    for (int u = 0; u < 96; ++u) {
        int r = u >> 5, lu = u & 31;
        float msu = __shfl_sync(0xffffffffu, ms[r], lu);
        float m0  = __shfl_sync(0xffffffffu, mv[r][0], lu);
        float m1  = __shfl_sync(0xffffffffu, mv[r][1], lu);
        float m2  = __shfl_sync(0xffffffffu, mv[r][2], lu);
        os0 += msu * W2s[u * OS + l];
        os1 += msu * W2s[u * OS + 32 + l];
        if (OS == 96) os2 += msu * W2s[u * OS + 64 + l];
        float wv = W2v[u * 32 + l];
        ov0 += m0 * wv; ov1 += m1 * wv; ov2 += m2 * wv;
    }

    float f = a * INV_S96;
    float sA = d_scs[n * OS + l]       + alpha * (os0 * f);
    float sB = d_scs[n * OS + 32 + l]  + alpha * (os1 * f);
    float sC = (OS == 96) ? (d_scs[n * OS + 64 + l] + alpha * (os2 * f)) : 0.f;
    float vv0 = d_scv[n * 96 + l * 3 + 0] + alpha * (ov0 * f);
    float vv1 = d_scv[n * 96 + l * 3 + 1] + alpha * (ov1 * f);
    float vv2 = d_scv[n * 96 + l * 3 + 2] + alpha * (ov2 * f);

    if (L1) {
        d_gs[n * 64 + l]      = siluf_(sA);
        d_gs[n * 64 + 32 + l] = siluf_(sB);
        float sg = sigmoidf_(sC);            // gate channels 64..95
        d_v1[n * 96 + l * 3 + 0] = vv0 * sg;
        d_v1[n * 96 + l * 3 + 1] = vv1 * sg;
        d_v1[n * 96 + l * 3 + 2] = vv2 * sg;
    } else {
        out[n * 160 + l]      = sA;
        out[n * 160 + 32 + l] = sB;
        out[n * 160 + 64 + l * 3 + 0] = vv0;
        out[n * 160 + 64 + l * 3 + 1] = vv1;
        out[n * 160 + 64 + l * 3 + 2] = vv2;
    }
}

// ---------------- launch ----------------------------------------------------
extern "C" void kernel_launch(void* const* d_in, const int* in_sizes, int n_in,
                              void* d_out, int out_size)
{
    const float* node_s = (const float*)d_in[0];
    const float* node_v = (const float*)d_in[1];
    const float* attr   = (const float*)d_in[2];
    const int*   src    = (const int*)d_in[3];
    const int*   dst    = (const int*)d_in[4];
    const float* sh     = (const float*)d_in[5];
    const float* esc    = (const float*)d_in[6];
    const float* w1[9];
    const float* w2[9];
    for (int i = 0; i < 9; ++i) { w1[i] = (const float*)d_in[7 + i]; w2[i] = (const float*)d_in[16 + i]; }
    float* out = (float*)d_out;

    cudaFuncSetAttribute(k_edge, cudaFuncAttributeMaxDynamicSharedMemorySize, B_SMEM_BYTES);

    k_deg_zero<<<(N_NODES + 255) / 256, 256>>>();
    k_deg<<<(N_EDGES + 255) / 256, 256>>>(dst);

    // ---- layer 1 (o_s = 96) ----
    k_node_pre<96, false><<<(N_NODES + 7) / 8, 256>>>(node_s, node_v, attr,
                                                      w1[0], w1[1], w1[2], w1[3]);
    k_edge<<<N_EDGES / EPB, 256, B_SMEM_BYTES>>>(esc, sh, src, dst, w1[4], w1[5]);
    k_node_post<96, true><<<(N_NODES + 7) / 8, 256>>>(attr, w1[6], w1[7], w1[8], out);

    // ---- layer 2 (o_s = 64) ----
    k_node_pre<64, true><<<(N_NODES + 7) / 8, 256>>>(nullptr, nullptr, attr,
                                                     w2[0], w2[1], w2[2], w2[3]);
    k_edge<<<N_EDGES / EPB, 256, B_SMEM_BYTES>>>(esc, sh, src, dst, w2[4], w2[5]);
    k_node_post<64, false><<<(N_NODES + 7) / 8, 256>>>(attr, w2[6], w2[7], w2[8], out);

    (void)in_sizes; (void)n_in; (void)out_size;
}

// round 4
// speedup vs baseline: 1.4617x; 1.0688x over previous
#include <cuda_runtime.h>
#include <math.h>
#include <stdint.h>

#define N_NODES 50000
#define N_EDGES 400000
#define EPB 64   // edges per block in k_edge

// Scale constants
#define INV_S64  0.125f                  // 1/sqrt(64)
#define INV_S32  0.17677669529663687f    // 1/sqrt(32)
#define INV_S10  0.31622776601683794f    // 1/sqrt(10)
#define INV_S96  0.10206207261596575f    // 1/sqrt(96)
#define INV_S3   0.57735026918962576f    // 1/sqrt(3)

// ---------------- scratch (device globals; no allocation allowed) ----------
__device__ float d_hs [N_NODES * 64];   // lin1 scalar features
__device__ float d_hv [N_NODES * 96];   // lin1 vector features (32 x 3)
__device__ float d_scs[N_NODES * 96];   // skip-connection scalars (stride = OS)
__device__ float d_scv[N_NODES * 96];   // skip-connection vectors
__device__ float d_Ms [N_NODES * 96];   // aggregated scalar messages
__device__ float d_Mv [N_NODES * 288];  // aggregated vector messages (96 x 3)
__device__ float d_deg[N_NODES];
__device__ float d_gs [N_NODES * 64];   // layer-1 -> layer-2 scalar input
__device__ float d_v1 [N_NODES * 96];   // layer-1 -> layer-2 vector input
__device__ float d_w2f[2][12288];       // Wfc2 tf32, MMA-fragment-packed, per layer

__device__ __forceinline__ float sigmoidf_(float x) { return 1.0f / (1.0f + __expf(-x)); }
__device__ __forceinline__ float siluf_(float x)    { return x / (1.0f + __expf(-x)); }

__device__ __forceinline__ float tf32r(float x) {
    uint32_t u;
    asm("cvt.rna.tf32.f32 %0, %1;" : "=r"(u) : "f"(x));
    return __uint_as_float(u);
}

__device__ __forceinline__ void mma_tf32(float c[4],
    uint32_t a0, uint32_t a1, uint32_t a2, uint32_t a3,
    uint32_t b0, uint32_t b1)
{
    asm volatile(
        "mma.sync.aligned.m16n8k8.row.col.f32.tf32.tf32.f32 "
        "{%0,%1,%2,%3},{%4,%5,%6,%7},{%8,%9},{%0,%1,%2,%3};"
        : "+f"(c[0]), "+f"(c[1]), "+f"(c[2]), "+f"(c[3])
        : "r"(a0), "r"(a1), "r"(a2), "r"(a3), "r"(b0), "r"(b1));
}

// ---------------- degree + weight prep -------------------------------------
__global__ void k_deg_zero() {
    int i = blockIdx.x * blockDim.x + threadIdx.x;
    if (i < N_NODES) d_deg[i] = 0.0f;
}
__global__ void k_deg(const int* __restrict__ dst) {
    int i = blockIdx.x * blockDim.x + threadIdx.x;
    if (i < N_EDGES) atomicAdd(&d_deg[dst[i]], 1.0f);
}

// Pack Wfc2 (64k x 192n) into MMA B-fragment order, tf32-rounded:
// idx = ((S*24 + T)*2 + half)*32 + lane, value = W[(8S + kc + 4*half)*192 + 8T + row]
// with row = lane>>2, kc = lane&3.
__global__ void k_prep(const float* __restrict__ W2a, const float* __restrict__ W2b) {
    int t = blockIdx.x * 256 + threadIdx.x;
    if (t >= 24576) return;
    int lay = t / 12288, r = t % 12288;
    int S = r / 1536;
    int rem = r % 1536;
    int T = rem / 64;
    int rem2 = rem % 64;
    int half = rem2 >> 5, lane = rem2 & 31;
    int row = lane >> 2, kc = lane & 3;
    const float* W = lay ? W2b : W2a;
    d_w2f[lay][r] = tf32r(W[(8 * S + kc + 4 * half) * 192 + 8 * T + row]);
}

// ---------------- kernel A: node pre-linears (warp per node) ---------------
template <int OS, bool SCR>
__global__ void __launch_bounds__(256) k_node_pre(
    const float* __restrict__ ns_in, const float* __restrict__ nv_in,
    const float* __restrict__ attr,
    const float* __restrict__ Wscs, const float* __restrict__ Wscv,
    const float* __restrict__ W1s,  const float* __restrict__ W1v)
{
    int n = blockIdx.x * 8 + (threadIdx.x >> 5);
    if (n >= N_NODES) return;
    int l = threadIdx.x & 31;

    const float* ns = SCR ? d_gs : ns_in;
    const float* nv = SCR ? d_v1 : nv_in;

    float a = attr[n];
    float ns0 = ns[n * 64 + l], ns1 = ns[n * 64 + 32 + l];
    float nv0 = nv[n * 96 + l * 3 + 0];
    float nv1 = nv[n * 96 + l * 3 + 1];
    float nv2 = nv[n * 96 + l * 3 + 2];

    float hs0 = 0.f, hs1 = 0.f;
    float sc0 = 0.f, sc1 = 0.f, sc2 = 0.f;
#pragma unroll
    for (int u = 0; u < 64; ++u) {
        float nsu = __shfl_sync(0xffffffffu, (u < 32) ? ns0 : ns1, u & 31);
        hs0 += nsu * W1s[u * 64 + l];
        hs1 += nsu * W1s[u * 64 + 32 + l];
        sc0 += nsu * Wscs[u * OS + l];
        sc1 += nsu * Wscs[u * OS + 32 + l];
        if (OS == 96) sc2 += nsu * Wscs[u * OS + 64 + l];
    }

    float hv0 = 0.f, hv1 = 0.f, hv2 = 0.f;
    float sv0 = 0.f, sv1 = 0.f, sv2 = 0.f;
#pragma unroll
    for (int u = 0; u < 32; ++u) {
        float b0 = __shfl_sync(0xffffffffu, nv0, u);
        float b1 = __shfl_sync(0xffffffffu, nv1, u);
        float b2 = __shfl_sync(0xffffffffu, nv2, u);
        float wl = W1v [u * 32 + l];
        float ws = Wscv[u * 32 + l];
        hv0 += b0 * wl; hv1 += b1 * wl; hv2 += b2 * wl;
        sv0 += b0 * ws; sv1 += b1 * ws; sv2 += b2 * ws;
    }

    float fs = a * INV_S64, fv = a * INV_S32;
    d_hs[n * 64 + l]       = hs0 * fs;
    d_hs[n * 64 + 32 + l]  = hs1 * fs;
    d_scs[n * OS + l]      = sc0 * fs;
    d_scs[n * OS + 32 + l] = sc1 * fs;
    if (OS == 96) d_scs[n * OS + 64 + l] = sc2 * fs;
    d_hv [n * 96 + l * 3 + 0] = hv0 * fv;
    d_hv [n * 96 + l * 3 + 1] = hv1 * fv;
    d_hv [n * 96 + l * 3 + 2] = hv2 * fv;
    d_scv[n * 96 + l * 3 + 0] = sv0 * fv;
    d_scv[n * 96 + l * 3 + 1] = sv1 * fv;
    d_scv[n * 96 + l * 3 + 2] = sv2 * fv;

    // zero accumulators for the edge pass
    d_Ms[n * 96 + l] = 0.f;
    d_Ms[n * 96 + 32 + l] = 0.f;
    d_Ms[n * 96 + 64 + l] = 0.f;
#pragma unroll
    for (int r = 0; r < 9; ++r) d_Mv[n * 288 + r * 32 + l] = 0.f;
}

// ---------------- kernel B: fused edge MLP (tf32 MMA) + messages + scatter -
// 64 edges / block, 256 threads (8 warps). 3 barriers total.
// smem floats: Wfc1 640 | esc 640 | hT 64*72 (k-major) | w 64*193
#define SH_STRIDE 72
#define B_SMEM_FLOATS (640 + 640 + 64*SH_STRIDE + 64*193)   // 18240
#define B_SMEM_BYTES  (B_SMEM_FLOATS * 4)                   // 72960

__global__ void __launch_bounds__(256, 2) k_edge(
    const float* __restrict__ esc, const float* __restrict__ sh,
    const int* __restrict__ src,   const int* __restrict__ dst,
    const float* __restrict__ Wfc1, int layer)
{
    extern __shared__ float sm[];
    float* s_w1  = sm;                        // 640  : Wfc1 (10 x 64)
    float* s_esc = sm + 640;                  // 640  : edge scalars (64 x 10)
    float* s_hT  = sm + 1280;                 // 4608 : hidden, TRANSPOSED [64 k][72]
    float* s_w   = sm + 1280 + 64*SH_STRIDE;  // 12352: weights w (64 rows, stride 193)

    const int t  = threadIdx.x;
    const int e0 = blockIdx.x * EPB;
    const int lane = t & 31, wp = t >> 5;

    for (int i = t; i < 640; i += 256) s_w1[i]  = Wfc1[i];
    for (int i = t; i < 640; i += 256) s_esc[i] = esc[e0 * 10 + i];
    __syncthreads();

    // ---- phase 1: h = silu(esc @ Wfc1 / sqrt(10)), tf32-rounded, transposed ----
    {
        int e = t & 63, q = t >> 6;     // 4 col-groups of 16
        float es[10];
#pragma unroll
        for (int u = 0; u < 10; ++u) es[u] = s_esc[e * 10 + u];
#pragma unroll
        for (int c = 0; c < 16; ++c) {
            int col = q * 16 + c;
            float acc = 0.f;
#pragma unroll
            for (int u = 0; u < 10; ++u) acc += es[u] * s_w1[u * 64 + col];
            s_hT[col * SH_STRIDE + e] = tf32r(siluf_(acc * INV_S10));
        }
    }
    __syncthreads();

    // ---- phase 2: w = h @ Wfc2 / 8 via tf32 m16n8k8 MMA ----
    // warp wp: m-tile (wp&3)*16, n-tiles T = (wp>>2)*12 .. +11, K=64 in one pass.
    // B operands: fragment-packed coalesced LDG from d_w2f (L1-resident).
    {
        const int m0   = (wp & 3) * 16;
        const int tb   = (wp >> 2) * 12;
        const int row  = lane >> 2, kc = lane & 3;
        const float* w2f = (const float*)d_w2f[layer];

        float c[12][4];
#pragma unroll
        for (int i = 0; i < 12; ++i)
#pragma unroll
            for (int j = 0; j < 4; ++j) c[i][j] = 0.f;

#pragma unroll
        for (int S = 0; S < 8; ++S) {
            int kk = S * 8;
            uint32_t a0 = __float_as_uint(s_hT[(kk + kc)     * SH_STRIDE + m0 + row]);
            uint32_t a1 = __float_as_uint(s_hT[(kk + kc)     * SH_STRIDE + m0 + row + 8]);
            uint32_t a2 = __float_as_uint(s_hT[(kk + kc + 4) * SH_STRIDE + m0 + row]);
            uint32_t a3 = __float_as_uint(s_hT[(kk + kc + 4) * SH_STRIDE + m0 + row + 8]);
#pragma unroll
            for (int tt = 0; tt < 12; ++tt) {
                int T = tb + tt;
                const float* bp = w2f + ((S * 24 + T) * 2) * 32 + lane;
                uint32_t b0 = __float_as_uint(__ldg(bp));
                uint32_t b1 = __float_as_uint(__ldg(bp + 32));
                mma_tf32(c[tt], a0, a1, a2, a3, b0, b1);
            }
        }
        // writeback C -> s_w (row: edge, col: weight channel), scaled by 1/8
#pragma unroll
        for (int tt = 0; tt < 12; ++tt) {
            int col = (tb + tt) * 8 + kc * 2;
            int r0  = m0 + row;
            s_w[r0 * 193 + col]           = c[tt][0] * INV_S64;
            s_w[r0 * 193 + col + 1]       = c[tt][1] * INV_S64;
            s_w[(r0 + 8) * 193 + col]     = c[tt][2] * INV_S64;
            s_w[(r0 + 8) * 193 + col + 1] = c[tt][3] * INV_S64;
        }
    }
    __syncthreads();

    // ---- phase 3: warp-per-edge messages + coalesced scalar scatter ----
    {
#pragma unroll
        for (int ei = 0; ei < 8; ++ei) {
            int e  = wp * 8 + ei;
            int ge = e0 + e;
            int sn = __ldg(src + ge), dn = __ldg(dst + ge);
            float4 sh4 = __ldg((const float4*)(sh + ge * 4));
            float s0 = sh4.x, vx = sh4.y, vy = sh4.z, vz = sh4.w;
            const float* we  = s_w + e * 193;
            const float* hsp = d_hs + sn * 64;
            const float* hvp = d_hv + sn * 96;
            float* msd = d_Ms + dn * 96;
            float* mvd = d_Mv + dn * 288;

            // Ms channels 0..63 : gs * sh0 * w1
            atomicAdd(msd + lane,      hsp[lane]      * s0 * we[lane]);
            atomicAdd(msd + 32 + lane, hsp[lane + 32] * s0 * we[lane + 32]);
            // Ms channels 64..95 : (gv . shv)/sqrt3 * w4
            {
                float h0 = hvp[lane * 3], h1 = hvp[lane * 3 + 1], h2 = hvp[lane * 3 + 2];
                atomicAdd(msd + 64 + lane,
                          (h0 * vx + h1 * vy + h2 * vz) * INV_S3 * we[160 + lane]);
            }
            // Mv flat 0..191 : gs[j] * shv[i] * w2[j]   (j = f/3, i = f%3)
#pragma unroll
            for (int r = 0; r < 6; ++r) {
                int f = r * 32 + lane;
                int j = f / 3, i = f - 3 * j;
                float shvi = (i == 0) ? vx : ((i == 1) ? vy : vz);
                atomicAdd(mvd + f, hsp[j] * shvi * we[64 + j]);
            }
            // Mv flat 192..287 : gv[jp][i] * sh0 * w3[jp]  (idx = jp*3+i)
#pragma unroll
            for (int r = 0; r < 3; ++r) {
                int idx = r * 32 + lane;
                atomicAdd(mvd + 192 + idx, hvp[idx] * s0 * we[128 + idx / 3]);
            }
        }
    }
}

// ---------------- kernel C: node finalize (warp per node) ------------------
template <int OS, bool L1>
__global__ void __launch_bounds__(256) k_node_post(
    const float* __restrict__ attr,
    const float* __restrict__ W2s, const float* __restrict__ W2v,
    const float* __restrict__ Wa,  float* __restrict__ out)
{
    int n = blockIdx.x * 8 + (threadIdx.x >> 5);
    if (n >= N_NODES) return;
    int l = threadIdx.x & 31;

    float a = attr[n];
    float invd = 1.0f / fmaxf(d_deg[n], 1.0f);

    float ms[3], mv[3][3];
#pragma unroll
    for (int r = 0; r < 3; ++r) {
        ms[r] = d_Ms[n * 96 + r * 32 + l] * invd;
#pragma unroll
        for (int i = 0; i < 3; ++i)
            mv[r][i] = d_Mv[n * 288 + (r * 32 + l) * 3 + i] * invd;
    }

    // alpha = (Ms . Wa) / sqrt(96) * attr
    float ap = ms[0] * Wa[l] + ms[1] * Wa[32 + l] + ms[2] * Wa[64 + l];
#pragma unroll
    for (int o = 16; o > 0; o >>= 1) ap += __shfl_xor_sync(0xffffffffu, ap, o);
    float alpha = ap * INV_S96 * a;

    float os0 = 0.f, os1 = 0.f, os2 = 0.f;
    float ov0 = 0.f, ov1 = 0.f, ov2 = 0.f;
#pragma unroll
    for (int u = 0; u < 96; ++u) {
        int r = u >> 5, lu = u & 31;
        float msu = __shfl_sync(0xffffffffu, ms[r], lu);
        float m0  = __shfl_sync(0xffffffffu, mv[r][0], lu);
        float m1  = __shfl_sync(0xffffffffu, mv[r][1], lu);
        float m2  = __shfl_sync(0xffffffffu, mv[r][2], lu);
        os0 += msu * W2s[u * OS + l];
        os1 += msu * W2s[u * OS + 32 + l];
        if (OS == 96) os2 += msu * W2s[u * OS + 64 + l];
        float wv = W2v[u * 32 + l];
        ov0 += m0 * wv; ov1 += m1 * wv; ov2 += m2 * wv;
    }

    float f = a * INV_S96;
    float sA = d_scs[n * OS + l]       + alpha * (os0 * f);
    float sB = d_scs[n * OS + 32 + l]  + alpha * (os1 * f);
    float sC = (OS == 96) ? (d_scs[n * OS + 64 + l] + alpha * (os2 * f)) : 0.f;
    float vv0 = d_scv[n * 96 + l * 3 + 0] + alpha * (ov0 * f);
    float vv1 = d_scv[n * 96 + l * 3 + 1] + alpha * (ov1 * f);
    float vv2 = d_scv[n * 96 + l * 3 + 2] + alpha * (ov2 * f);

    if (L1) {
        d_gs[n * 64 + l]      = siluf_(sA);
        d_gs[n * 64 + 32 + l] = siluf_(sB);
        float sg = sigmoidf_(sC);            // gate channels 64..95
        d_v1[n * 96 + l * 3 + 0] = vv0 * sg;
        d_v1[n * 96 + l * 3 + 1] = vv1 * sg;
        d_v1[n * 96 + l * 3 + 2] = vv2 * sg;
    } else {
        out[n * 160 + l]      = sA;
        out[n * 160 + 32 + l] = sB;
        out[n * 160 + 64 + l * 3 + 0] = vv0;
        out[n * 160 + 64 + l * 3 + 1] = vv1;
        out[n * 160 + 64 + l * 3 + 2] = vv2;
    }
}

// ---------------- launch ----------------------------------------------------
extern "C" void kernel_launch(void* const* d_in, const int* in_sizes, int n_in,
                              void* d_out, int out_size)
{
    const float* node_s = (const float*)d_in[0];
    const float* node_v = (const float*)d_in[1];
    const float* attr   = (const float*)d_in[2];
    const int*   src    = (const int*)d_in[3];
    const int*   dst    = (const int*)d_in[4];
    const float* sh     = (const float*)d_in[5];
    const float* esc    = (const float*)d_in[6];
    const float* w1[9];
    const float* w2[9];
    for (int i = 0; i < 9; ++i) { w1[i] = (const float*)d_in[7 + i]; w2[i] = (const float*)d_in[16 + i]; }
    float* out = (float*)d_out;

    cudaFuncSetAttribute(k_edge, cudaFuncAttributeMaxDynamicSharedMemorySize, B_SMEM_BYTES);

    k_deg_zero<<<(N_NODES + 255) / 256, 256>>>();
    k_deg<<<(N_EDGES + 255) / 256, 256>>>(dst);
    k_prep<<<96, 256>>>(w1[5], w2[5]);

    // ---- layer 1 (o_s = 96) ----
    k_node_pre<96, false><<<(N_NODES + 7) / 8, 256>>>(node_s, node_v, attr,
                                                      w1[0], w1[1], w1[2], w1[3]);
    k_edge<<<N_EDGES / EPB, 256, B_SMEM_BYTES>>>(esc, sh, src, dst, w1[4], 0);
    k_node_post<96, true><<<(N_NODES + 7) / 8, 256>>>(attr, w1[6], w1[7], w1[8], out);

    // ---- layer 2 (o_s = 64) ----
    k_node_pre<64, true><<<(N_NODES + 7) / 8, 256>>>(nullptr, nullptr, attr,
                                                     w2[0], w2[1], w2[2], w2[3]);
    k_edge<<<N_EDGES / EPB, 256, B_SMEM_BYTES>>>(esc, sh, src, dst, w2[4], 1);
    k_node_post<64, false><<<(N_NODES + 7) / 8, 256>>>(attr, w2[6], w2[7], w2[8], out);

    (void)in_sizes; (void)n_in; (void)out_size;
}

// round 5
// speedup vs baseline: 1.7308x; 1.1841x over previous
#include <cuda_runtime.h>
#include <math.h>
#include <stdint.h>

#define N_NODES 50000
#define N_EDGES 400000
#define EPB 64   // edges per block in k_edge

// Scale constants
#define INV_S64  0.125f                  // 1/sqrt(64)
#define INV_S32  0.17677669529663687f    // 1/sqrt(32)
#define INV_S10  0.31622776601683794f    // 1/sqrt(10)
#define INV_S96  0.10206207261596575f    // 1/sqrt(96)
#define INV_S3   0.57735026918962576f    // 1/sqrt(3)

// ---------------- scratch (device globals; no allocation allowed) ----------
__device__ float d_hs [N_NODES * 64];   // lin1 scalar features
__device__ float d_hv [N_NODES * 96];   // lin1 vector features (32 x 3)
__device__ float d_scs[N_NODES * 96];   // skip-connection scalars (stride = OS)
__device__ float d_scv[N_NODES * 96];   // skip-connection vectors
__device__ float d_Ms [N_NODES * 96];   // aggregated scalar messages
__device__ float d_Mv [N_NODES * 288];  // aggregated vector messages (96 x 3)
__device__ float d_deg[N_NODES];
__device__ float d_gs [N_NODES * 64];   // layer-1 -> layer-2 scalar input
__device__ float d_v1 [N_NODES * 96];   // layer-1 -> layer-2 vector input
__device__ float d_w2f[2][12288];       // Wfc2 tf32, MMA-fragment-packed, per layer

__device__ __forceinline__ float sigmoidf_(float x) { return 1.0f / (1.0f + __expf(-x)); }
__device__ __forceinline__ float siluf_(float x)    { return x / (1.0f + __expf(-x)); }

__device__ __forceinline__ float tf32r(float x) {
    uint32_t u;
    asm("cvt.rna.tf32.f32 %0, %1;" : "=r"(u) : "f"(x));
    return __uint_as_float(u);
}

__device__ __forceinline__ void mma_tf32(float c[4],
    uint32_t a0, uint32_t a1, uint32_t a2, uint32_t a3,
    uint32_t b0, uint32_t b1)
{
    asm volatile(
        "mma.sync.aligned.m16n8k8.row.col.f32.tf32.tf32.f32 "
        "{%0,%1,%2,%3},{%4,%5,%6,%7},{%8,%9},{%0,%1,%2,%3};"
        : "+f"(c[0]), "+f"(c[1]), "+f"(c[2]), "+f"(c[3])
        : "r"(a0), "r"(a1), "r"(a2), "r"(a3), "r"(b0), "r"(b1));
}

__device__ __forceinline__ void red4(float* p, float4 v) {
    atomicAdd(reinterpret_cast<float4*>(p), v);
}

// ---------------- degree + weight prep -------------------------------------
__global__ void k_deg_zero() {
    int i = blockIdx.x * blockDim.x + threadIdx.x;
    if (i < N_NODES) d_deg[i] = 0.0f;
}
__global__ void k_deg(const int* __restrict__ dst) {
    int i = blockIdx.x * blockDim.x + threadIdx.x;
    if (i < N_EDGES) atomicAdd(&d_deg[dst[i]], 1.0f);
}

// Pack Wfc2 (64k x 192n) into MMA B-fragment order, tf32-rounded.
__global__ void k_prep(const float* __restrict__ W2a, const float* __restrict__ W2b) {
    int t = blockIdx.x * 256 + threadIdx.x;
    if (t >= 24576) return;
    int lay = t / 12288, r = t % 12288;
    int S = r / 1536;
    int rem = r % 1536;
    int T = rem / 64;
    int rem2 = rem % 64;
    int half = rem2 >> 5, lane = rem2 & 31;
    int row = lane >> 2, kc = lane & 3;
    const float* W = lay ? W2b : W2a;
    d_w2f[lay][r] = tf32r(W[(8 * S + kc + 4 * half) * 192 + 8 * T + row]);
}

// ---------------- kernel A: node pre-linears (warp per 2 nodes) ------------
template <int OS, bool SCR>
__global__ void __launch_bounds__(256) k_node_pre(
    const float* __restrict__ ns_in, const float* __restrict__ nv_in,
    const float* __restrict__ attr,
    const float* __restrict__ Wscs, const float* __restrict__ Wscv,
    const float* __restrict__ W1s,  const float* __restrict__ W1v)
{
    const int l  = threadIdx.x & 31;
    const int n0 = (blockIdx.x * 8 + (threadIdx.x >> 5)) * 2;
    if (n0 >= N_NODES) return;
    const bool actB = (n0 + 1 < N_NODES);
    const int nA = n0, nB = actB ? n0 + 1 : n0;

    const float* ns = SCR ? d_gs : ns_in;
    const float* nv = SCR ? d_v1 : nv_in;

    float aA = attr[nA], aB = attr[nB];
    float nsA0 = ns[nA * 64 + l], nsA1 = ns[nA * 64 + 32 + l];
    float nsB0 = ns[nB * 64 + l], nsB1 = ns[nB * 64 + 32 + l];
    float nvA0 = nv[nA * 96 + l * 3 + 0], nvA1 = nv[nA * 96 + l * 3 + 1], nvA2 = nv[nA * 96 + l * 3 + 2];
    float nvB0 = nv[nB * 96 + l * 3 + 0], nvB1 = nv[nB * 96 + l * 3 + 1], nvB2 = nv[nB * 96 + l * 3 + 2];

    float hsA0 = 0.f, hsA1 = 0.f, scA0 = 0.f, scA1 = 0.f, scA2 = 0.f;
    float hsB0 = 0.f, hsB1 = 0.f, scB0 = 0.f, scB1 = 0.f, scB2 = 0.f;
#pragma unroll
    for (int u = 0; u < 64; ++u) {
        float w1a = W1s[u * 64 + l];
        float w1b = W1s[u * 64 + 32 + l];
        float wsa = Wscs[u * OS + l];
        float wsb = Wscs[u * OS + 32 + l];
        float wsc = (OS == 96) ? Wscs[u * OS + 64 + l] : 0.f;
        float nuA = __shfl_sync(0xffffffffu, (u < 32) ? nsA0 : nsA1, u & 31);
        float nuB = __shfl_sync(0xffffffffu, (u < 32) ? nsB0 : nsB1, u & 31);
        hsA0 += nuA * w1a; hsA1 += nuA * w1b;
        scA0 += nuA * wsa; scA1 += nuA * wsb;
        hsB0 += nuB * w1a; hsB1 += nuB * w1b;
        scB0 += nuB * wsa; scB1 += nuB * wsb;
        if (OS == 96) { scA2 += nuA * wsc; scB2 += nuB * wsc; }
    }

    float hvA0 = 0.f, hvA1 = 0.f, hvA2 = 0.f, svA0 = 0.f, svA1 = 0.f, svA2 = 0.f;
    float hvB0 = 0.f, hvB1 = 0.f, hvB2 = 0.f, svB0 = 0.f, svB1 = 0.f, svB2 = 0.f;
#pragma unroll
    for (int u = 0; u < 32; ++u) {
        float wl = W1v [u * 32 + l];
        float ws = Wscv[u * 32 + l];
        float bA0 = __shfl_sync(0xffffffffu, nvA0, u);
        float bA1 = __shfl_sync(0xffffffffu, nvA1, u);
        float bA2 = __shfl_sync(0xffffffffu, nvA2, u);
        float bB0 = __shfl_sync(0xffffffffu, nvB0, u);
        float bB1 = __shfl_sync(0xffffffffu, nvB1, u);
        float bB2 = __shfl_sync(0xffffffffu, nvB2, u);
        hvA0 += bA0 * wl; hvA1 += bA1 * wl; hvA2 += bA2 * wl;
        svA0 += bA0 * ws; svA1 += bA1 * ws; svA2 += bA2 * ws;
        hvB0 += bB0 * wl; hvB1 += bB1 * wl; hvB2 += bB2 * wl;
        svB0 += bB0 * ws; svB1 += bB1 * ws; svB2 += bB2 * ws;
    }

    {
        float fs = aA * INV_S64, fv = aA * INV_S32;
        d_hs[nA * 64 + l]       = hsA0 * fs;
        d_hs[nA * 64 + 32 + l]  = hsA1 * fs;
        d_scs[nA * OS + l]      = scA0 * fs;
        d_scs[nA * OS + 32 + l] = scA1 * fs;
        if (OS == 96) d_scs[nA * OS + 64 + l] = scA2 * fs;
        d_hv [nA * 96 + l * 3 + 0] = hvA0 * fv;
        d_hv [nA * 96 + l * 3 + 1] = hvA1 * fv;
        d_hv [nA * 96 + l * 3 + 2] = hvA2 * fv;
        d_scv[nA * 96 + l * 3 + 0] = svA0 * fv;
        d_scv[nA * 96 + l * 3 + 1] = svA1 * fv;
        d_scv[nA * 96 + l * 3 + 2] = svA2 * fv;
        d_Ms[nA * 96 + l] = 0.f; d_Ms[nA * 96 + 32 + l] = 0.f; d_Ms[nA * 96 + 64 + l] = 0.f;
#pragma unroll
        for (int r = 0; r < 9; ++r) d_Mv[nA * 288 + r * 32 + l] = 0.f;
    }
    if (actB) {
        float fs = aB * INV_S64, fv = aB * INV_S32;
        d_hs[nB * 64 + l]       = hsB0 * fs;
        d_hs[nB * 64 + 32 + l]  = hsB1 * fs;
        d_scs[nB * OS + l]      = scB0 * fs;
        d_scs[nB * OS + 32 + l] = scB1 * fs;
        if (OS == 96) d_scs[nB * OS + 64 + l] = scB2 * fs;
        d_hv [nB * 96 + l * 3 + 0] = hvB0 * fv;
        d_hv [nB * 96 + l * 3 + 1] = hvB1 * fv;
        d_hv [nB * 96 + l * 3 + 2] = hvB2 * fv;
        d_scv[nB * 96 + l * 3 + 0] = svB0 * fv;
        d_scv[nB * 96 + l * 3 + 1] = svB1 * fv;
        d_scv[nB * 96 + l * 3 + 2] = svB2 * fv;
        d_Ms[nB * 96 + l] = 0.f; d_Ms[nB * 96 + 32 + l] = 0.f; d_Ms[nB * 96 + 64 + l] = 0.f;
#pragma unroll
        for (int r = 0; r < 9; ++r) d_Mv[nB * 288 + r * 32 + l] = 0.f;
    }
}

// ---------------- kernel B: fused edge MLP (tf32 MMA) + messages + scatter -
// 64 edges / block, 256 threads (8 warps). 3 barriers. s_w stride 196 (16B rows).
#define SH_STRIDE 72
#define SW_STRIDE 196
#define B_SMEM_FLOATS (640 + 640 + 64*SH_STRIDE + 64*SW_STRIDE)  // 18432
#define B_SMEM_BYTES  (B_SMEM_FLOATS * 4)                        // 73728

__global__ void __launch_bounds__(256, 3) k_edge(
    const float* __restrict__ esc, const float* __restrict__ sh,
    const int* __restrict__ src,   const int* __restrict__ dst,
    const float* __restrict__ Wfc1, int layer)
{
    extern __shared__ float sm[];
    float* s_w1  = sm;                        // 640  : Wfc1 (10 x 64)
    float* s_esc = sm + 640;                  // 640  : edge scalars (64 x 10)
    float* s_hT  = sm + 1280;                 // 4608 : hidden, TRANSPOSED [64 k][72]
    float* s_w   = sm + 1280 + 64*SH_STRIDE;  // 12544: weights w (64 rows, stride 196)

    const int t  = threadIdx.x;
    const int e0 = blockIdx.x * EPB;
    const int lane = t & 31, wp = t >> 5;

    for (int i = t; i < 640; i += 256) s_w1[i]  = Wfc1[i];
    for (int i = t; i < 640; i += 256) s_esc[i] = esc[e0 * 10 + i];
    __syncthreads();

    // ---- phase 1: h = silu(esc @ Wfc1 / sqrt(10)), tf32-rounded, transposed ----
    {
        int e = t & 63, q = t >> 6;
        float es[10];
#pragma unroll
        for (int u = 0; u < 10; ++u) es[u] = s_esc[e * 10 + u];
#pragma unroll
        for (int c = 0; c < 16; ++c) {
            int col = q * 16 + c;
            float acc = 0.f;
#pragma unroll
            for (int u = 0; u < 10; ++u) acc += es[u] * s_w1[u * 64 + col];
            s_hT[col * SH_STRIDE + e] = tf32r(siluf_(acc * INV_S10));
        }
    }
    __syncthreads();

    // ---- phase 2: w = h @ Wfc2 / 8 via tf32 m16n8k8 MMA ----
    {
        const int m0   = (wp & 3) * 16;
        const int tb   = (wp >> 2) * 12;
        const int row  = lane >> 2, kc = lane & 3;
        const float* w2f = (const float*)d_w2f[layer];

        float c[12][4];
#pragma unroll
        for (int i = 0; i < 12; ++i)
#pragma unroll
            for (int j = 0; j < 4; ++j) c[i][j] = 0.f;

#pragma unroll
        for (int S = 0; S < 8; ++S) {
            int kk = S * 8;
            uint32_t a0 = __float_as_uint(s_hT[(kk + kc)     * SH_STRIDE + m0 + row]);
            uint32_t a1 = __float_as_uint(s_hT[(kk + kc)     * SH_STRIDE + m0 + row + 8]);
            uint32_t a2 = __float_as_uint(s_hT[(kk + kc + 4) * SH_STRIDE + m0 + row]);
            uint32_t a3 = __float_as_uint(s_hT[(kk + kc + 4) * SH_STRIDE + m0 + row + 8]);
#pragma unroll
            for (int tt = 0; tt < 12; ++tt) {
                int T = tb + tt;
                const float* bp = w2f + ((S * 24 + T) * 2) * 32 + lane;
                uint32_t b0 = __float_as_uint(__ldg(bp));
                uint32_t b1 = __float_as_uint(__ldg(bp + 32));
                mma_tf32(c[tt], a0, a1, a2, a3, b0, b1);
            }
        }
#pragma unroll
        for (int tt = 0; tt < 12; ++tt) {
            int col = (tb + tt) * 8 + kc * 2;
            int r0  = m0 + row;
            s_w[r0 * SW_STRIDE + col]           = c[tt][0] * INV_S64;
            s_w[r0 * SW_STRIDE + col + 1]       = c[tt][1] * INV_S64;
            s_w[(r0 + 8) * SW_STRIDE + col]     = c[tt][2] * INV_S64;
            s_w[(r0 + 8) * SW_STRIDE + col + 1] = c[tt][3] * INV_S64;
        }
    }
    __syncthreads();

    // ---- phase 3: warp-per-edge messages, vectorized red.v4 scatter ----
    {
#pragma unroll
        for (int ei = 0; ei < 8; ++ei) {
            int e  = wp * 8 + ei;
            int ge = e0 + e;
            int sn = __ldg(src + ge), dn = __ldg(dst + ge);
            float4 sh4 = __ldg((const float4*)(sh + ge * 4));
            float s0 = sh4.x, vx = sh4.y, vy = sh4.z, vz = sh4.w;
            const float* we  = s_w + e * SW_STRIDE;
            const float* hsp = d_hs + sn * 64;
            const float* hvp = d_hv + sn * 96;
            float* msd = d_Ms + dn * 96;
            float* mvd = d_Mv + dn * 288;

            // Ms 0..63 (16 lanes) / Ms 64..95 dot (8 lanes)
            if (lane < 16) {
                int j0 = lane * 4;
                float4 h4 = *(const float4*)(hsp + j0);
                float4 wa = *(const float4*)(we + j0);
                red4(msd + j0, make_float4(h4.x * s0 * wa.x, h4.y * s0 * wa.y,
                                           h4.z * s0 * wa.z, h4.w * s0 * wa.w));
            } else if (lane < 24) {
                int jp0 = (lane - 16) * 4;
                const float* gp = hvp + jp0 * 3;
                float4 ga = *(const float4*)gp;
                float4 gb = *(const float4*)(gp + 4);
                float4 gc = *(const float4*)(gp + 8);
                float4 w4 = *(const float4*)(we + 160 + jp0);
                float4 v;
                v.x = (ga.x * vx + ga.y * vy + ga.z * vz) * INV_S3 * w4.x;
                v.y = (ga.w * vx + gb.x * vy + gb.y * vz) * INV_S3 * w4.y;
                v.z = (gb.z * vx + gb.w * vy + gc.x * vz) * INV_S3 * w4.z;
                v.w = (gc.y * vx + gc.z * vy + gc.w * vz) * INV_S3 * w4.w;
                red4(msd + 64 + jp0, v);
            }
            // Mv flat 0..127 (all lanes) and 128..191 (16 lanes):
            // mvd[f] += hsp[f/3] * shv[f%3] * we[64 + f/3]
            {
                int f0 = lane * 4;
                float v[4];
#pragma unroll
                for (int c2 = 0; c2 < 4; ++c2) {
                    int f = f0 + c2, j = f / 3, i2 = f - 3 * j;
                    float shvi = (i2 == 0) ? vx : ((i2 == 1) ? vy : vz);
                    v[c2] = hsp[j] * shvi * we[64 + j];
                }
                red4(mvd + f0, make_float4(v[0], v[1], v[2], v[3]));
                if (lane < 16) {
                    int f1 = 128 + lane * 4;
                    float u2[4];
#pragma unroll
                    for (int c2 = 0; c2 < 4; ++c2) {
                        int f = f1 + c2, j = f / 3, i2 = f - 3 * j;
                        float shvi = (i2 == 0) ? vx : ((i2 == 1) ? vy : vz);
                        u2[c2] = hsp[j] * shvi * we[64 + j];
                    }
                    red4(mvd + f1, make_float4(u2[0], u2[1], u2[2], u2[3]));
                }
            }
            // Mv flat 192..287 (24 lanes): mvd[192+i] += hvp[i]*s0*we[128+i/3]
            if (lane < 24) {
                int i0 = lane * 4;
                float4 g4 = *(const float4*)(hvp + i0);
                float4 v;
                v.x = g4.x * s0 * we[128 + (i0    ) / 3];
                v.y = g4.y * s0 * we[128 + (i0 + 1) / 3];
                v.z = g4.z * s0 * we[128 + (i0 + 2) / 3];
                v.w = g4.w * s0 * we[128 + (i0 + 3) / 3];
                red4(mvd + 192 + i0, v);
            }
        }
    }
}

// ---------------- kernel C: node finalize (warp per 2 nodes) ---------------
template <int OS, bool L1>
__global__ void __launch_bounds__(256) k_node_post(
    const float* __restrict__ attr,
    const float* __restrict__ W2s, const float* __restrict__ W2v,
    const float* __restrict__ Wa,  float* __restrict__ out)
{
    const int l  = threadIdx.x & 31;
    const int n0 = (blockIdx.x * 8 + (threadIdx.x >> 5)) * 2;
    if (n0 >= N_NODES) return;
    const bool actB = (n0 + 1 < N_NODES);
    const int nA = n0, nB = actB ? n0 + 1 : n0;

    float aA = attr[nA], aB = attr[nB];
    float idA = 1.0f / fmaxf(d_deg[nA], 1.0f);
    float idB = 1.0f / fmaxf(d_deg[nB], 1.0f);

    float msA[3], msB[3], mvA[3][3], mvB[3][3];
#pragma unroll
    for (int r = 0; r < 3; ++r) {
        msA[r] = d_Ms[nA * 96 + r * 32 + l] * idA;
        msB[r] = d_Ms[nB * 96 + r * 32 + l] * idB;
#pragma unroll
        for (int i = 0; i < 3; ++i) {
            mvA[r][i] = d_Mv[nA * 288 + (r * 32 + l) * 3 + i] * idA;
            mvB[r][i] = d_Mv[nB * 288 + (r * 32 + l) * 3 + i] * idB;
        }
    }

    float wa0 = Wa[l], wa1 = Wa[32 + l], wa2 = Wa[64 + l];
    float apA = msA[0] * wa0 + msA[1] * wa1 + msA[2] * wa2;
    float apB = msB[0] * wa0 + msB[1] * wa1 + msB[2] * wa2;
#pragma unroll
    for (int o = 16; o > 0; o >>= 1) {
        apA += __shfl_xor_sync(0xffffffffu, apA, o);
        apB += __shfl_xor_sync(0xffffffffu, apB, o);
    }
    float alA = apA * INV_S96 * aA;
    float alB = apB * INV_S96 * aB;

    float osA0 = 0.f, osA1 = 0.f, osA2 = 0.f, ovA0 = 0.f, ovA1 = 0.f, ovA2 = 0.f;
    float osB0 = 0.f, osB1 = 0.f, osB2 = 0.f, ovB0 = 0.f, ovB1 = 0.f, ovB2 = 0.f;
#pragma unroll
    for (int u = 0; u < 96; ++u) {
        int r = u >> 5, lu = u & 31;
        float w0 = W2s[u * OS + l];
        float w1 = W2s[u * OS + 32 + l];
        float w2 = (OS == 96) ? W2s[u * OS + 64 + l] : 0.f;
        float wv = W2v[u * 32 + l];
        float mA  = __shfl_sync(0xffffffffu, msA[r], lu);
        float mB  = __shfl_sync(0xffffffffu, msB[r], lu);
        float vA0 = __shfl_sync(0xffffffffu, mvA[r][0], lu);
        float vA1 = __shfl_sync(0xffffffffu, mvA[r][1], lu);
        float vA2 = __shfl_sync(0xffffffffu, mvA[r][2], lu);
        float vB0 = __shfl_sync(0xffffffffu, mvB[r][0], lu);
        float vB1 = __shfl_sync(0xffffffffu, mvB[r][1], lu);
        float vB2 = __shfl_sync(0xffffffffu, mvB[r][2], lu);
        osA0 += mA * w0; osA1 += mA * w1;
        osB0 += mB * w0; osB1 += mB * w1;
        if (OS == 96) { osA2 += mA * w2; osB2 += mB * w2; }
        ovA0 += vA0 * wv; ovA1 += vA1 * wv; ovA2 += vA2 * wv;
        ovB0 += vB0 * wv; ovB1 += vB1 * wv; ovB2 += vB2 * wv;
    }

    {
        float f = aA * INV_S96;
        float sA = d_scs[nA * OS + l]      + alA * (osA0 * f);
        float sB = d_scs[nA * OS + 32 + l] + alA * (osA1 * f);
        float sC = (OS == 96) ? (d_scs[nA * OS + 64 + l] + alA * (osA2 * f)) : 0.f;
        float v0 = d_scv[nA * 96 + l * 3 + 0] + alA * (ovA0 * f);
        float v1 = d_scv[nA * 96 + l * 3 + 1] + alA * (ovA1 * f);
        float v2 = d_scv[nA * 96 + l * 3 + 2] + alA * (ovA2 * f);
        if (L1) {
            d_gs[nA * 64 + l]      = siluf_(sA);
            d_gs[nA * 64 + 32 + l] = siluf_(sB);
            float sg = sigmoidf_(sC);
            d_v1[nA * 96 + l * 3 + 0] = v0 * sg;
            d_v1[nA * 96 + l * 3 + 1] = v1 * sg;
            d_v1[nA * 96 + l * 3 + 2] = v2 * sg;
        } else {
            out[nA * 160 + l]      = sA;
            out[nA * 160 + 32 + l] = sB;
            out[nA * 160 + 64 + l * 3 + 0] = v0;
            out[nA * 160 + 64 + l * 3 + 1] = v1;
            out[nA * 160 + 64 + l * 3 + 2] = v2;
        }
    }
    if (actB) {
        float f = aB * INV_S96;
        float sA = d_scs[nB * OS + l]      + alB * (osB0 * f);
        float sB2 = d_scs[nB * OS + 32 + l] + alB * (osB1 * f);
        float sC = (OS == 96) ? (d_scs[nB * OS + 64 + l] + alB * (osB2 * f)) : 0.f;
        float v0 = d_scv[nB * 96 + l * 3 + 0] + alB * (ovB0 * f);
        float v1 = d_scv[nB * 96 + l * 3 + 1] + alB * (ovB1 * f);
        float v2 = d_scv[nB * 96 + l * 3 + 2] + alB * (ovB2 * f);
        if (L1) {
            d_gs[nB * 64 + l]      = siluf_(sA);
            d_gs[nB * 64 + 32 + l] = siluf_(sB2);
            float sg = sigmoidf_(sC);
            d_v1[nB * 96 + l * 3 + 0] = v0 * sg;
            d_v1[nB * 96 + l * 3 + 1] = v1 * sg;
            d_v1[nB * 96 + l * 3 + 2] = v2 * sg;
        } else {
            out[nB * 160 + l]      = sA;
            out[nB * 160 + 32 + l] = sB2;
            out[nB * 160 + 64 + l * 3 + 0] = v0;
            out[nB * 160 + 64 + l * 3 + 1] = v1;
            out[nB * 160 + 64 + l * 3 + 2] = v2;
        }
    }
}

// ---------------- launch ----------------------------------------------------
extern "C" void kernel_launch(void* const* d_in, const int* in_sizes, int n_in,
                              void* d_out, int out_size)
{
    const float* node_s = (const float*)d_in[0];
    const float* node_v = (const float*)d_in[1];
    const float* attr   = (const float*)d_in[2];
    const int*   src    = (const int*)d_in[3];
    const int*   dst    = (const int*)d_in[4];
    const float* sh     = (const float*)d_in[5];
    const float* esc    = (const float*)d_in[6];
    const float* w1[9];
    const float* w2[9];
    for (int i = 0; i < 9; ++i) { w1[i] = (const float*)d_in[7 + i]; w2[i] = (const float*)d_in[16 + i]; }
    float* out = (float*)d_out;

    cudaFuncSetAttribute(k_edge, cudaFuncAttributeMaxDynamicSharedMemorySize, B_SMEM_BYTES);

    const int NPB = 16;  // nodes per block (8 warps x 2)
    const int nodeBlocks = (N_NODES + NPB - 1) / NPB;

    k_deg_zero<<<(N_NODES + 255) / 256, 256>>>();
    k_deg<<<(N_EDGES + 255) / 256, 256>>>(dst);
    k_prep<<<96, 256>>>(w1[5], w2[5]);

    // ---- layer 1 (o_s = 96) ----
    k_node_pre<96, false><<<nodeBlocks, 256>>>(node_s, node_v, attr,
                                               w1[0], w1[1], w1[2], w1[3]);
    k_edge<<<N_EDGES / EPB, 256, B_SMEM_BYTES>>>(esc, sh, src, dst, w1[4], 0);
    k_node_post<96, true><<<nodeBlocks, 256>>>(attr, w1[6], w1[7], w1[8], out);

    // ---- layer 2 (o_s = 64) ----
    k_node_pre<64, true><<<nodeBlocks, 256>>>(nullptr, nullptr, attr,
                                              w2[0], w2[1], w2[2], w2[3]);
    k_edge<<<N_EDGES / EPB, 256, B_SMEM_BYTES>>>(esc, sh, src, dst, w2[4], 1);
    k_node_post<64, false><<<nodeBlocks, 256>>>(attr, w2[6], w2[7], w2[8], out);

    (void)in_sizes; (void)n_in; (void)out_size;
}